// round 11
// baseline (speedup 1.0000x reference)
#include <cuda_runtime.h>
#include <cuda_fp16.h>
#include <math.h>
#include <stdint.h>

// Problem constants
#define B_    2
#define D_    8
#define C_    128
#define NH_   8
#define NTOK  65536
#define NWIN  512
#define NN_   128
#define MLPH  512

// ---------------- scratch (device globals) -----------------------------------
__device__ half  g_qkvh[24LL * NTOK * 16];    // [part(3)][head(8)][tok][16]
__device__ float g_bias[NH_ * NN_ * NN_];     // [h][n(query)][m(key)]
__device__ half  g_attn[NTOK * C_];
__device__ float g_x1[NTOK * C_];
__device__ half  g_xn2[NTOK * C_];
__device__ half  g_hid[(long)NTOK * MLPH];
// fp16 weights
__device__ half  g_qkvw[384 * C_];
__device__ half  g_projw[C_ * C_];
__device__ half  g_fc1w[MLPH * C_];
__device__ half  g_fc2w[C_ * MLPH];

__device__ __forceinline__ float gelu_exact(float x) {
    return 0.5f * x * (1.0f + erff(x * 0.70710678118654752f));
}

// ---- mma.sync m16n8k16 f16 -> f32 ------------------------------------------------
#define MMA(d, a, b)                                                            \
    asm volatile("mma.sync.aligned.m16n8k16.row.col.f32.f16.f16.f32 "           \
        "{%0,%1,%2,%3}, {%4,%5,%6,%7}, {%8,%9}, {%0,%1,%2,%3};"                 \
        : "+f"((d)[0]), "+f"((d)[1]), "+f"((d)[2]), "+f"((d)[3])                \
        : "r"((a)[0]), "r"((a)[1]), "r"((a)[2]), "r"((a)[3]),                    \
          "r"((b)[0]), "r"((b)[1]))

#define LDMX4(r, addr)                                                          \
    asm volatile("ldmatrix.sync.aligned.m8n8.x4.shared.b16 {%0,%1,%2,%3}, [%4];"\
        : "=r"((r)[0]), "=r"((r)[1]), "=r"((r)[2]), "=r"((r)[3]) : "r"(addr))
#define LDMX2(r, addr)                                                          \
    asm volatile("ldmatrix.sync.aligned.m8n8.x2.shared.b16 {%0,%1}, [%2];"      \
        : "=r"((r)[0]), "=r"((r)[1]) : "r"(addr))

__device__ __forceinline__ uint32_t packh2(float v0, float v1) {
    half2 h = __floats2half2_rn(v0, v1);
    return *(uint32_t*)&h;
}
__device__ __forceinline__ uint32_t smem_u32(const void* p) {
    uint32_t a;
    asm("{ .reg .u64 t; cvta.to.shared.u64 t, %1; cvt.u32.u64 %0, t; }" : "=r"(a) : "l"(p));
    return a;
}
__device__ __forceinline__ void cpa16(uint32_t d, const void* s) {
    asm volatile("cp.async.cg.shared.global [%0], [%1], 16;" :: "r"(d), "l"(s));
}
#define CP_COMMIT() asm volatile("cp.async.commit_group;" ::: "memory")
#define CP_WAIT0()  asm volatile("cp.async.wait_group 0;" ::: "memory")
#define CP_WAIT1()  asm volatile("cp.async.wait_group 1;" ::: "memory")

#define PADK 72
#define BUFB (128 * PADK * 2)     // bytes per stage per tile

// ==================  generic GEMM (fc1 / fc2)  ====================================
// OMODE: 0 = f32 row-major, 1 = fp16 row-major
template <int ACT, bool RES, int OMODE>
__global__ void __launch_bounds__(256, 2)
mma_gemm(const half* __restrict__ A, const half* __restrict__ W,
         const float* __restrict__ bias, const float* __restrict__ res,
         float* __restrict__ Cf, half* __restrict__ Chf,
         int N, int K) {
    extern __shared__ half smem[];
    half* sA = smem;
    half* sW = smem + 2 * 128 * PADK;
    uint32_t sAu = smem_u32(sA), sWu = smem_u32(sW);

    int tid = threadIdx.x, wid = tid >> 5, lane = tid & 31;
    int g = lane >> 2, t = lane & 3;
    int m0 = blockIdx.y * 128, n0 = blockIdx.x * 128;
    int wm = (wid & 1) * 64, wn = (wid >> 1) * 32;

    float acc[4][4][4];
#pragma unroll
    for (int i = 0; i < 4; i++)
#pragma unroll
        for (int j = 0; j < 4; j++)
#pragma unroll
            for (int c = 0; c < 4; c++) acc[i][j][c] = 0.0f;

    int crow = tid >> 3, cseg = (tid & 7) * 8;
    auto issue = [&](int kc, int buf) {
#pragma unroll
        for (int i = 0; i < 4; i++) {
            int row = crow + i * 32;
            uint32_t so = (uint32_t)buf * BUFB + (row * PADK + cseg) * 2;
            cpa16(sAu + so, A + (long)(m0 + row) * K + kc + cseg);
            cpa16(sWu + so, W + (long)(n0 + row) * K + kc + cseg);
        }
        CP_COMMIT();
    };

    int lrow = lane & 7, lsel = lane >> 3;
    uint32_t aBase = sAu + ((wm + (lsel & 1) * 8 + lrow) * PADK + (lsel >> 1) * 8) * 2;
    uint32_t bBase = sWu + ((wn + lrow) * PADK + (lsel & 1) * 8) * 2;

    int nch = K >> 6;
    issue(0, 0);
    for (int c = 0; c < nch; c++) {
        if (c + 1 < nch) { issue((c + 1) << 6, (c + 1) & 1); CP_WAIT1(); }
        else             { CP_WAIT0(); }
        __syncthreads();
        uint32_t bofs = (uint32_t)(c & 1) * BUFB;
#pragma unroll
        for (int ks = 0; ks < 4; ks++) {
            uint32_t kb2 = ks * 32;
            uint32_t fa[4][4], fb[4][2];
#pragma unroll
            for (int mi = 0; mi < 4; mi++)
                LDMX4(fa[mi], aBase + bofs + mi * (16 * PADK * 2) + kb2);
#pragma unroll
            for (int nj = 0; nj < 4; nj++)
                LDMX2(fb[nj], bBase + bofs + nj * (8 * PADK * 2) + kb2);
#pragma unroll
            for (int mi = 0; mi < 4; mi++)
#pragma unroll
                for (int nj = 0; nj < 4; nj++)
                    MMA(acc[mi][nj], fa[mi], fb[nj]);
        }
        __syncthreads();
    }

#pragma unroll
    for (int mi = 0; mi < 4; mi++) {
#pragma unroll
        for (int cr = 0; cr < 2; cr++) {
            int m = m0 + wm + mi * 16 + g + cr * 8;
#pragma unroll
            for (int nj = 0; nj < 4; nj++) {
                int n = n0 + wn + nj * 8 + 2 * t;
                float2 bb = *(const float2*)(bias + n);
                float v0 = acc[mi][nj][cr * 2 + 0] + bb.x;
                float v1 = acc[mi][nj][cr * 2 + 1] + bb.y;
                if (ACT == 1) { v0 = gelu_exact(v0); v1 = gelu_exact(v1); }
                if (RES) {
                    float2 r = *(const float2*)(res + (long)m * N + n);
                    v0 += r.x; v1 += r.y;
                }
                if (OMODE == 1) {
                    *(half2*)(Chf + (long)m * N + n) = __floats2half2_rn(v0, v1);
                } else {
                    float2 o; o.x = v0; o.y = v1;
                    *(float2*)(Cf + (long)m * N + n) = o;
                }
            }
        }
    }
}

// ==================  QKV GEMM with fused LN1 + cyclic shift  ======================
// A rows = LN1(x[shift-gather]) computed in prologue; K=128 fully resident.
__global__ void __launch_bounds__(256, 2)
qkv_ln_gemm(const float* __restrict__ x, const float* __restrict__ lg,
            const float* __restrict__ lb, const float* __restrict__ bias) {
    extern __shared__ half smem[];
    half* sA = smem;
    half* sW = smem + 2 * 128 * PADK;
    uint32_t sAu = smem_u32(sA), sWu = smem_u32(sW);

    int tid = threadIdx.x, wid = tid >> 5, lane = tid & 31;
    int g = lane >> 2, t = lane & 3;
    int m0 = blockIdx.y * 128, n0 = blockIdx.x * 128;
    int wm = (wid & 1) * 64, wn = (wid >> 1) * 32;

    // W: both K-stages via cp.async (overlaps with LN prologue)
    int crow = tid >> 3, cseg = (tid & 7) * 8;
#pragma unroll
    for (int s = 0; s < 2; s++)
#pragma unroll
        for (int i = 0; i < 4; i++) {
            int row = crow + i * 32;
            cpa16(sWu + s * BUFB + (row * PADK + cseg) * 2,
                  g_qkvw + (long)(n0 + row) * 128 + s * 64 + cseg);
        }
    CP_COMMIT();

    // LN1 + shift prologue: warp per row, 16 rows/warp
    float4 gg = *(const float4*)(lg + lane * 4);
    float4 bv = *(const float4*)(lb + lane * 4);
    int k0 = lane * 4;
    uint32_t abyte = (k0 >= 64 ? BUFB : 0u) + (uint32_t)(k0 & 63) * 2;
    for (int i = 0; i < 16; i++) {
        int r = wid * 16 + i;
        int m = m0 + r;
        int bw = m >> 7, n = m & 127;
        int bb = bw >> 8, wi = bw & 255;
        int sd = (wi >> 6) * 2 + (n >> 6);
        int sh = ((wi >> 3) & 7) * 8 + ((n >> 3) & 7);
        int sw = (wi & 7) * 8 + (n & 7);
        int gd = (sd + 1) & 7, gh = (sh + 4) & 63, gw = (sw + 4) & 63;
        long src = (((long)(bb * 8 + gd) * 64 + gh) * 64 + gw) * 128;
        float4 v = *(const float4*)(x + src + k0);
        float s  = v.x + v.y + v.z + v.w;
        float sq = v.x * v.x + v.y * v.y + v.z * v.z + v.w * v.w;
#pragma unroll
        for (int o = 16; o > 0; o >>= 1) {
            s  += __shfl_xor_sync(0xffffffffu, s, o);
            sq += __shfl_xor_sync(0xffffffffu, sq, o);
        }
        float mean = s * (1.0f / 128.0f);
        float var  = sq * (1.0f / 128.0f) - mean * mean;
        float inv  = rsqrtf(var + 1e-5f);
        uint2 pk;
        pk.x = packh2((v.x - mean) * inv * gg.x + bv.x,
                      (v.y - mean) * inv * gg.y + bv.y);
        pk.y = packh2((v.z - mean) * inv * gg.z + bv.z,
                      (v.w - mean) * inv * gg.w + bv.w);
        *(uint2*)((char*)sA + (uint32_t)r * (PADK * 2) + abyte) = pk;
    }
    CP_WAIT0();
    __syncthreads();

    float acc[4][4][4];
#pragma unroll
    for (int i = 0; i < 4; i++)
#pragma unroll
        for (int j = 0; j < 4; j++)
#pragma unroll
            for (int c = 0; c < 4; c++) acc[i][j][c] = 0.0f;

    int lrow = lane & 7, lsel = lane >> 3;
    uint32_t aBase = sAu + ((wm + (lsel & 1) * 8 + lrow) * PADK + (lsel >> 1) * 8) * 2;
    uint32_t bBase = sWu + ((wn + lrow) * PADK + (lsel & 1) * 8) * 2;

#pragma unroll
    for (int c = 0; c < 2; c++) {
        uint32_t bofs = (uint32_t)c * BUFB;
#pragma unroll
        for (int ks = 0; ks < 4; ks++) {
            uint32_t kb2 = ks * 32;
            uint32_t fa[4][4], fb[4][2];
#pragma unroll
            for (int mi = 0; mi < 4; mi++)
                LDMX4(fa[mi], aBase + bofs + mi * (16 * PADK * 2) + kb2);
#pragma unroll
            for (int nj = 0; nj < 4; nj++)
                LDMX2(fb[nj], bBase + bofs + nj * (8 * PADK * 2) + kb2);
#pragma unroll
            for (int mi = 0; mi < 4; mi++)
#pragma unroll
                for (int nj = 0; nj < 4; nj++)
                    MMA(acc[mi][nj], fa[mi], fb[nj]);
        }
    }

    // epilogue: head-major fp16, q scaled by 0.25
#pragma unroll
    for (int mi = 0; mi < 4; mi++) {
#pragma unroll
        for (int cr = 0; cr < 2; cr++) {
            int m = m0 + wm + mi * 16 + g + cr * 8;
#pragma unroll
            for (int nj = 0; nj < 4; nj++) {
                int n = n0 + wn + nj * 8 + 2 * t;
                float2 bb = *(const float2*)(bias + n);
                float v0 = acc[mi][nj][cr * 2 + 0] + bb.x;
                float v1 = acc[mi][nj][cr * 2 + 1] + bb.y;
                if (n < 128) { v0 *= 0.25f; v1 *= 0.25f; }
                int p = n >> 7, hh = (n >> 4) & 7, d = n & 15;
                long addr = ((long)(p * 8 + hh) * NTOK + m) * 16 + d;
                *(half2*)(g_qkvh + addr) = __floats2half2_rn(v0, v1);
            }
        }
    }
}

// ==================  proj GEMM with fused residual + reverse-roll + LN2  ==========
// N = 128 (full rows per CTA); writes g_x1 (f32) and g_xn2 (fp16) directly.
__global__ void __launch_bounds__(256, 2)
proj_ln2_gemm(const float* __restrict__ x, const float* __restrict__ g2,
              const float* __restrict__ b2, const float* __restrict__ bias) {
    extern __shared__ half smem[];
    half* sA = smem;
    half* sW = smem + 2 * 128 * PADK;
    uint32_t sAu = smem_u32(sA), sWu = smem_u32(sW);

    int tid = threadIdx.x, wid = tid >> 5, lane = tid & 31;
    int g = lane >> 2, t = lane & 3;
    int m0 = blockIdx.y * 128;
    int wm = (wid & 1) * 64, wn = (wid >> 1) * 32;

    // load A (attn out) and W, both K-stages (K=128)
    int crow = tid >> 3, cseg = (tid & 7) * 8;
#pragma unroll
    for (int s = 0; s < 2; s++)
#pragma unroll
        for (int i = 0; i < 4; i++) {
            int row = crow + i * 32;
            uint32_t so = s * BUFB + (row * PADK + cseg) * 2;
            cpa16(sAu + so, g_attn + (long)(m0 + row) * 128 + s * 64 + cseg);
            cpa16(sWu + so, g_projw + (long)row * 128 + s * 64 + cseg);
        }
    CP_COMMIT();
    CP_WAIT0();
    __syncthreads();

    float acc[4][4][4];
#pragma unroll
    for (int i = 0; i < 4; i++)
#pragma unroll
        for (int j = 0; j < 4; j++)
#pragma unroll
            for (int c = 0; c < 4; c++) acc[i][j][c] = 0.0f;

    int lrow = lane & 7, lsel = lane >> 3;
    uint32_t aBase = sAu + ((wm + (lsel & 1) * 8 + lrow) * PADK + (lsel >> 1) * 8) * 2;
    uint32_t bBase = sWu + ((wn + lrow) * PADK + (lsel & 1) * 8) * 2;

#pragma unroll
    for (int c = 0; c < 2; c++) {
        uint32_t bofs = (uint32_t)c * BUFB;
#pragma unroll
        for (int ks = 0; ks < 4; ks++) {
            uint32_t kb2 = ks * 32;
            uint32_t fa[4][4], fb[4][2];
#pragma unroll
            for (int mi = 0; mi < 4; mi++)
                LDMX4(fa[mi], aBase + bofs + mi * (16 * PADK * 2) + kb2);
#pragma unroll
            for (int nj = 0; nj < 4; nj++)
                LDMX2(fb[nj], bBase + bofs + nj * (8 * PADK * 2) + kb2);
#pragma unroll
            for (int mi = 0; mi < 4; mi++)
#pragma unroll
                for (int nj = 0; nj < 4; nj++)
                    MMA(acc[mi][nj], fa[mi], fb[nj]);
        }
    }
    __syncthreads();   // smem reuse barrier

    // stage acc (+proj bias) into smem as f32 tile [128][132]
    float* sT = (float*)smem;
#pragma unroll
    for (int mi = 0; mi < 4; mi++) {
#pragma unroll
        for (int cr = 0; cr < 2; cr++) {
            int ml = wm + mi * 16 + g + cr * 8;
#pragma unroll
            for (int nj = 0; nj < 4; nj++) {
                int n = wn + nj * 8 + 2 * t;
                float2 bb = *(const float2*)(bias + n);
                float2 o;
                o.x = acc[mi][nj][cr * 2 + 0] + bb.x;
                o.y = acc[mi][nj][cr * 2 + 1] + bb.y;
                *(float2*)(sT + ml * 132 + n) = o;
            }
        }
    }
    __syncthreads();

    // fused: residual(x via inverse roll) + LN2, warp per row
    float4 gg = *(const float4*)(g2 + lane * 4);
    float4 bv = *(const float4*)(b2 + lane * 4);
    for (int i = 0; i < 16; i++) {
        int r = wid * 16 + i;
        int m = m0 + r;
        int bw = m >> 7, n = m & 127;
        int bb = bw >> 8, wi = bw & 255;
        int sd = (wi >> 6) * 2 + (n >> 6);
        int sh = ((wi >> 3) & 7) * 8 + ((n >> 3) & 7);
        int sw = (wi & 7) * 8 + (n & 7);
        int dd = (sd + 1) & 7, hh = (sh + 4) & 63, ww2 = (sw + 4) & 63;
        long tok = ((long)(bb * 8 + dd) * 64 + hh) * 64 + ww2;

        float4 v  = *(const float4*)(sT + r * 132 + lane * 4);
        float4 xv = *(const float4*)(x + tok * 128 + lane * 4);
        float4 s1;
        s1.x = v.x + xv.x; s1.y = v.y + xv.y;
        s1.z = v.z + xv.z; s1.w = v.w + xv.w;
        *(float4*)(g_x1 + tok * 128 + lane * 4) = s1;

        float s  = s1.x + s1.y + s1.z + s1.w;
        float sq = s1.x * s1.x + s1.y * s1.y + s1.z * s1.z + s1.w * s1.w;
#pragma unroll
        for (int o = 16; o > 0; o >>= 1) {
            s  += __shfl_xor_sync(0xffffffffu, s, o);
            sq += __shfl_xor_sync(0xffffffffu, sq, o);
        }
        float mean = s * (1.0f / 128.0f);
        float var  = sq * (1.0f / 128.0f) - mean * mean;
        float inv  = rsqrtf(var + 1e-5f);
        long o = tok * 128 + lane * 4;
        *(half2*)(g_xn2 + o)     = __floats2half2_rn((s1.x - mean) * inv * gg.x + bv.x,
                                                     (s1.y - mean) * inv * gg.y + bv.y);
        *(half2*)(g_xn2 + o + 2) = __floats2half2_rn((s1.z - mean) * inv * gg.z + bv.z,
                                                     (s1.w - mean) * inv * gg.w + bv.w);
    }
}

// ---------------- weight convert (one launch) -----------------------------------
__global__ void convert_weights(const float* __restrict__ qkv_w,
                                const float* __restrict__ proj_w,
                                const float* __restrict__ fc1_w,
                                const float* __restrict__ fc2_w) {
    int i = blockIdx.x * blockDim.x + threadIdx.x;   // 0..65535
    if (i < 49152) g_qkvw[i] = __float2half(qkv_w[i]);
    if (i < 16384) g_projw[i] = __float2half(proj_w[i]);
    g_fc1w[i] = __float2half(fc1_w[i]);
    g_fc2w[i] = __float2half(fc2_w[i]);
}

// ---------------- bias table ([h][query][key]) -----------------------------------
__global__ void bias_kernel(const float* __restrict__ rpb) {
    int n = blockIdx.x;    // query
    int m = threadIdx.x;   // key
    int nd = n >> 6, nh = (n >> 3) & 7, nw = n & 7;
    int md = m >> 6, mh = (m >> 3) & 7, mw = m & 7;
    int rpi = (nd - md + 1) * 225 + (nh - mh + 7) * 15 + (nw - mw + 7);
#pragma unroll
    for (int h = 0; h < NH_; h++)
        g_bias[((long)h * NN_ + n) * NN_ + m] = rpb[rpi * NH_ + h];
}

// ---------------- tensor-core attention, CTA=(window,head), 8 warps --------------
#define VPAD 136
__global__ void __launch_bounds__(256) attn_kernel() {
    __shared__ half sVt[16 * VPAD];
    __shared__ int  lab[NN_];

    int bw = blockIdx.x >> 3;
    int h  = blockIdx.x & 7;
    int tid = threadIdx.x, wid = tid >> 5, lane = tid & 31;
    int g = lane >> 2, t = lane & 3;
    long tokbase = (long)bw * 128;
    const half* Qp = g_qkvh + ((long)h * NTOK + tokbase) * 16;
    const half* Kp = g_qkvh + ((long)(8 + h) * NTOK + tokbase) * 16;
    const half* Vp = g_qkvh + ((long)(16 + h) * NTOK + tokbase) * 16;

    {
        int tok = tid >> 1;
        int d0  = (tid & 1) * 8;
        uint4 hv = *(const uint4*)(Vp + tok * 16 + d0);
        const half* hp = (const half*)&hv;
#pragma unroll
        for (int d = 0; d < 8; d++)
            sVt[(d0 + d) * VPAD + tok] = hp[d];
    }
    if (tid < 128) {
        int wi = bw & 255;
        int sd = (wi >> 6) * 2 + (tid >> 6);
        int sh = ((wi >> 3) & 7) * 8 + ((tid >> 3) & 7);
        int sw = (wi & 7) * 8 + (tid & 7);
        int ld = sd < 6 ? 0 : (sd < 7 ? 1 : 2);
        int lh = sh < 56 ? 0 : (sh < 60 ? 1 : 2);
        int lw = sw < 56 ? 0 : (sw < 60 ? 1 : 2);
        lab[tid] = ld * 9 + lh * 3 + lw;
    }
    __syncthreads();

    int row0 = wid * 16;
    uint32_t qf[4];
    qf[0] = *(const uint32_t*)(Qp + (row0 + g) * 16 + 2 * t);
    qf[1] = *(const uint32_t*)(Qp + (row0 + g + 8) * 16 + 2 * t);
    qf[2] = *(const uint32_t*)(Qp + (row0 + g) * 16 + 2 * t + 8);
    qf[3] = *(const uint32_t*)(Qp + (row0 + g + 8) * 16 + 2 * t + 8);

    float acc[16][4];
#pragma unroll
    for (int j = 0; j < 16; j++) {
        uint32_t kf[2];
        kf[0] = *(const uint32_t*)(Kp + (8 * j + g) * 16 + 2 * t);
        kf[1] = *(const uint32_t*)(Kp + (8 * j + g) * 16 + 2 * t + 8);
        acc[j][0] = acc[j][1] = acc[j][2] = acc[j][3] = 0.0f;
        MMA(acc[j], qf, kf);
    }

    int myl_g  = lab[row0 + g];
    int myl_g8 = lab[row0 + g + 8];
    const float* bptr = g_bias + (long)h * NN_ * NN_;
    float sum_g = 0.0f, sum_g8 = 0.0f;
#pragma unroll
    for (int j = 0; j < 16; j++) {
        int col = 8 * j + 2 * t;
        float2 bg  = *(const float2*)(bptr + (row0 + g) * NN_ + col);
        float2 bg8 = *(const float2*)(bptr + (row0 + g + 8) * NN_ + col);
        int l0 = lab[col], l1 = lab[col + 1];
        float e0 = (l0 == myl_g)  ? __expf(acc[j][0] + bg.x)  : 0.0f;
        float e1 = (l1 == myl_g)  ? __expf(acc[j][1] + bg.y)  : 0.0f;
        float e2 = (l0 == myl_g8) ? __expf(acc[j][2] + bg8.x) : 0.0f;
        float e3 = (l1 == myl_g8) ? __expf(acc[j][3] + bg8.y) : 0.0f;
        acc[j][0] = e0; acc[j][1] = e1; acc[j][2] = e2; acc[j][3] = e3;
        sum_g += e0 + e1; sum_g8 += e2 + e3;
    }
    sum_g  += __shfl_xor_sync(0xffffffffu, sum_g, 1);
    sum_g  += __shfl_xor_sync(0xffffffffu, sum_g, 2);
    sum_g8 += __shfl_xor_sync(0xffffffffu, sum_g8, 1);
    sum_g8 += __shfl_xor_sync(0xffffffffu, sum_g8, 2);
    float rs_g = 1.0f / sum_g, rs_g8 = 1.0f / sum_g8;

    float oacc[2][4];
#pragma unroll
    for (int nj = 0; nj < 2; nj++)
#pragma unroll
        for (int c = 0; c < 4; c++) oacc[nj][c] = 0.0f;

#pragma unroll
    for (int kt = 0; kt < 8; kt++) {
        float* p0 = acc[2 * kt];
        float* p1 = acc[2 * kt + 1];
        uint32_t pf[4];
        pf[0] = packh2(p0[0], p0[1]);
        pf[1] = packh2(p0[2], p0[3]);
        pf[2] = packh2(p1[0], p1[1]);
        pf[3] = packh2(p1[2], p1[3]);
#pragma unroll
        for (int nj = 0; nj < 2; nj++) {
            int vb = (8 * nj + g) * VPAD + 16 * kt + 2 * t;
            uint32_t vf[2];
            vf[0] = *(const uint32_t*)&sVt[vb];
            vf[1] = *(const uint32_t*)&sVt[vb + 8];
            MMA(oacc[nj], pf, vf);
        }
    }

    long og  = (tokbase + row0 + g) * 128 + h * 16;
    long og8 = og + 8 * 128;
#pragma unroll
    for (int nj = 0; nj < 2; nj++) {
        int dn = 8 * nj + 2 * t;
        *(half2*)(g_attn + og + dn)  = __floats2half2_rn(oacc[nj][0] * rs_g,
                                                         oacc[nj][1] * rs_g);
        *(half2*)(g_attn + og8 + dn) = __floats2half2_rn(oacc[nj][2] * rs_g8,
                                                         oacc[nj][3] * rs_g8);
    }
}

// ---------------------------------------------------------------------------
extern "C" void kernel_launch(void* const* d_in, const int* in_sizes, int n_in,
                              void* d_out, int out_size) {
    const float* x      = (const float*)d_in[0];
    const float* qkv_w  = (const float*)d_in[1];
    const float* qkv_b  = (const float*)d_in[2];
    const float* proj_w = (const float*)d_in[3];
    const float* proj_b = (const float*)d_in[4];
    const float* rpb    = (const float*)d_in[5];
    const float* ln1_g  = (const float*)d_in[6];
    const float* ln1_b  = (const float*)d_in[7];
    const float* ln2_g  = (const float*)d_in[8];
    const float* ln2_b  = (const float*)d_in[9];
    const float* fc1_w  = (const float*)d_in[10];
    const float* fc1_b  = (const float*)d_in[11];
    const float* fc2_w  = (const float*)d_in[12];
    const float* fc2_b  = (const float*)d_in[13];
    float* out = (float*)d_out;

    half *p_xn2, *p_hid, *p_fc1w, *p_fc2w;
    float *p_x1;
    cudaGetSymbolAddress((void**)&p_xn2,  g_xn2);
    cudaGetSymbolAddress((void**)&p_hid,  g_hid);
    cudaGetSymbolAddress((void**)&p_fc1w, g_fc1w);
    cudaGetSymbolAddress((void**)&p_fc2w, g_fc2w);
    cudaGetSymbolAddress((void**)&p_x1,   g_x1);

    const int SMEM = 4 * 128 * PADK * 2;   // 73728 B
    cudaFuncSetAttribute(qkv_ln_gemm,  cudaFuncAttributeMaxDynamicSharedMemorySize, SMEM);
    cudaFuncSetAttribute(proj_ln2_gemm, cudaFuncAttributeMaxDynamicSharedMemorySize, SMEM);
    cudaFuncSetAttribute(mma_gemm<1, false, 1>, cudaFuncAttributeMaxDynamicSharedMemorySize, SMEM);
    cudaFuncSetAttribute(mma_gemm<0, true, 0>,  cudaFuncAttributeMaxDynamicSharedMemorySize, SMEM);

    // 0) weight convert + bias table
    convert_weights<<<256, 256>>>(qkv_w, proj_w, fc1_w, fc2_w);
    bias_kernel<<<128, 128>>>(rpb);

    // 1) QKV GEMM with fused LN1 + shift (-> head-major fp16, q pre-scaled)
    qkv_ln_gemm<<<dim3(3, 512), 256, SMEM>>>(x, ln1_g, ln1_b, qkv_b);
    // 2) attention (tensor cores)
    attn_kernel<<<NWIN * NH_, 256>>>();
    // 3) proj GEMM with fused residual + reverse-roll + LN2 (-> g_x1, g_xn2)
    proj_ln2_gemm<<<dim3(1, 512), 256, SMEM>>>(x, ln2_g, ln2_b, proj_b);
    // 4) fc1 + GELU -> fp16
    mma_gemm<1, false, 1><<<dim3(4, 512), 256, SMEM>>>(
        p_xn2, p_fc1w, fc1_b, nullptr, nullptr, p_hid, 512, 128);
    // 5) fc2 + residual -> out (f32)
    mma_gemm<0, true, 0><<<dim3(1, 512), 256, SMEM>>>(
        p_hid, p_fc2w, fc2_b, p_x1, out, nullptr, 128, 512);
}

// round 12
// speedup vs baseline: 1.2259x; 1.2259x over previous
#include <cuda_runtime.h>
#include <cuda_fp16.h>
#include <math.h>
#include <stdint.h>

// Problem constants
#define B_    2
#define D_    8
#define C_    128
#define NH_   8
#define NTOK  65536
#define NWIN  512
#define NN_   128
#define MLPH  512

// ---------------- scratch (device globals) -----------------------------------
__device__ half  g_win[NTOK * C_];
__device__ half  g_qkvh[24LL * NTOK * 16];    // [part(3)][head(8)][tok][16]
__device__ half  g_biash[NH_ * NN_ * NN_];    // [h][n(query)][m(key)] fp16
__device__ half  g_attn[NTOK * C_];
__device__ float g_projout[NTOK * C_];
__device__ float g_x1[NTOK * C_];
__device__ half  g_xn2[NTOK * C_];
__device__ half  g_hid[(long)NTOK * MLPH];
// fp16 weights
__device__ half  g_qkvw[384 * C_];
__device__ half  g_projw[C_ * C_];
__device__ half  g_fc1w[MLPH * C_];
__device__ half  g_fc2w[C_ * MLPH];

__device__ __forceinline__ float gelu_exact(float x) {
    return 0.5f * x * (1.0f + erff(x * 0.70710678118654752f));
}

// ---- mma.sync m16n8k16 f16 -> f32 ------------------------------------------------
#define MMA(d, a, b)                                                            \
    asm volatile("mma.sync.aligned.m16n8k16.row.col.f32.f16.f16.f32 "           \
        "{%0,%1,%2,%3}, {%4,%5,%6,%7}, {%8,%9}, {%0,%1,%2,%3};"                 \
        : "+f"((d)[0]), "+f"((d)[1]), "+f"((d)[2]), "+f"((d)[3])                \
        : "r"((a)[0]), "r"((a)[1]), "r"((a)[2]), "r"((a)[3]),                    \
          "r"((b)[0]), "r"((b)[1]))

#define LDMX4(r, addr)                                                          \
    asm volatile("ldmatrix.sync.aligned.m8n8.x4.shared.b16 {%0,%1,%2,%3}, [%4];"\
        : "=r"((r)[0]), "=r"((r)[1]), "=r"((r)[2]), "=r"((r)[3]) : "r"(addr))
#define LDMX2(r, addr)                                                          \
    asm volatile("ldmatrix.sync.aligned.m8n8.x2.shared.b16 {%0,%1}, [%2];"      \
        : "=r"((r)[0]), "=r"((r)[1]) : "r"(addr))

__device__ __forceinline__ uint32_t packh2(float v0, float v1) {
    half2 h = __floats2half2_rn(v0, v1);
    return *(uint32_t*)&h;
}
__device__ __forceinline__ uint32_t smem_u32(const void* p) {
    uint32_t a;
    asm("{ .reg .u64 t; cvta.to.shared.u64 t, %1; cvt.u32.u64 %0, t; }" : "=r"(a) : "l"(p));
    return a;
}
__device__ __forceinline__ void cpa16(uint32_t d, const void* s) {
    asm volatile("cp.async.cg.shared.global [%0], [%1], 16;" :: "r"(d), "l"(s));
}
#define CP_COMMIT() asm volatile("cp.async.commit_group;" ::: "memory")
#define CP_WAIT0()  asm volatile("cp.async.wait_group 0;" ::: "memory")
#define CP_WAIT1()  asm volatile("cp.async.wait_group 1;" ::: "memory")

// ==================  GEMM: fp16, double-buffered BK=64 pipeline  ==================
#define PADK 72
#define BUFB (128 * PADK * 2)

template <int ACT, bool RES, int OMODE>
__global__ void __launch_bounds__(256, 2)
mma_gemm(const half* __restrict__ A, const half* __restrict__ W,
         const float* __restrict__ bias, const float* __restrict__ res,
         float* __restrict__ Cf, half* __restrict__ Chf,
         int N, int K) {
    extern __shared__ half smem[];
    half* sA = smem;
    half* sW = smem + 2 * 128 * PADK;
    uint32_t sAu = smem_u32(sA), sWu = smem_u32(sW);

    int tid = threadIdx.x, wid = tid >> 5, lane = tid & 31;
    int g = lane >> 2, t = lane & 3;
    int m0 = blockIdx.y * 128, n0 = blockIdx.x * 128;
    int wm = (wid & 1) * 64, wn = (wid >> 1) * 32;

    float acc[4][4][4];
#pragma unroll
    for (int i = 0; i < 4; i++)
#pragma unroll
        for (int j = 0; j < 4; j++)
#pragma unroll
            for (int c = 0; c < 4; c++) acc[i][j][c] = 0.0f;

    int crow = tid >> 3, cseg = (tid & 7) * 8;
    auto issue = [&](int kc, int buf) {
#pragma unroll
        for (int i = 0; i < 4; i++) {
            int row = crow + i * 32;
            uint32_t so = (uint32_t)buf * BUFB + (row * PADK + cseg) * 2;
            cpa16(sAu + so, A + (long)(m0 + row) * K + kc + cseg);
            cpa16(sWu + so, W + (long)(n0 + row) * K + kc + cseg);
        }
        CP_COMMIT();
    };

    int lrow = lane & 7, lsel = lane >> 3;
    uint32_t aBase = sAu + ((wm + (lsel & 1) * 8 + lrow) * PADK + (lsel >> 1) * 8) * 2;
    uint32_t bBase = sWu + ((wn + lrow) * PADK + (lsel & 1) * 8) * 2;

    int nch = K >> 6;
    issue(0, 0);
    for (int c = 0; c < nch; c++) {
        if (c + 1 < nch) { issue((c + 1) << 6, (c + 1) & 1); CP_WAIT1(); }
        else             { CP_WAIT0(); }
        __syncthreads();
        uint32_t bofs = (uint32_t)(c & 1) * BUFB;
#pragma unroll
        for (int ks = 0; ks < 4; ks++) {
            uint32_t kb2 = ks * 32;
            uint32_t fa[4][4], fb[4][2];
#pragma unroll
            for (int mi = 0; mi < 4; mi++)
                LDMX4(fa[mi], aBase + bofs + mi * (16 * PADK * 2) + kb2);
#pragma unroll
            for (int nj = 0; nj < 4; nj++)
                LDMX2(fb[nj], bBase + bofs + nj * (8 * PADK * 2) + kb2);
#pragma unroll
            for (int mi = 0; mi < 4; mi++)
#pragma unroll
                for (int nj = 0; nj < 4; nj++)
                    MMA(acc[mi][nj], fa[mi], fb[nj]);
        }
        __syncthreads();
    }

#pragma unroll
    for (int mi = 0; mi < 4; mi++) {
#pragma unroll
        for (int cr = 0; cr < 2; cr++) {
            int m = m0 + wm + mi * 16 + g + cr * 8;
#pragma unroll
            for (int nj = 0; nj < 4; nj++) {
                int n = n0 + wn + nj * 8 + 2 * t;
                float2 bb = *(const float2*)(bias + n);
                float v0 = acc[mi][nj][cr * 2 + 0] + bb.x;
                float v1 = acc[mi][nj][cr * 2 + 1] + bb.y;
                if (OMODE == 2 && n < 128) { v0 *= 0.25f; v1 *= 0.25f; }
                if (ACT == 1) { v0 = gelu_exact(v0); v1 = gelu_exact(v1); }
                if (RES) {
                    float2 r = *(const float2*)(res + (long)m * N + n);
                    v0 += r.x; v1 += r.y;
                }
                if (OMODE == 2) {
                    int p = n >> 7, hh = (n >> 4) & 7, d = n & 15;
                    long addr = ((long)(p * 8 + hh) * NTOK + m) * 16 + d;
                    *(half2*)(Chf + addr) = __floats2half2_rn(v0, v1);
                } else if (OMODE == 1) {
                    *(half2*)(Chf + (long)m * N + n) = __floats2half2_rn(v0, v1);
                } else {
                    float2 o; o.x = v0; o.y = v1;
                    *(float2*)(Cf + (long)m * N + n) = o;
                }
            }
        }
    }
}

// ---------------- weight convert ------------------------------------------------
__global__ void convert_weights(const float* __restrict__ qkv_w,
                                const float* __restrict__ proj_w,
                                const float* __restrict__ fc1_w,
                                const float* __restrict__ fc2_w) {
    int i = blockIdx.x * blockDim.x + threadIdx.x;
    if (i < 49152) g_qkvw[i] = __float2half(qkv_w[i]);
    if (i < 16384) g_projw[i] = __float2half(proj_w[i]);
    g_fc1w[i] = __float2half(fc1_w[i]);
    g_fc2w[i] = __float2half(fc2_w[i]);
}

// ---------------- K1: LN1 + cyclic shift + window partition (-> fp16) ------------
__global__ void ln_gather_kernel(const float* __restrict__ x,
                                 const float* __restrict__ g,
                                 const float* __restrict__ b) {
    int warp = (blockIdx.x * blockDim.x + threadIdx.x) >> 5;
    int lane = threadIdx.x & 31;
    if (warp >= NWIN * NN_) return;
    int bw = warp >> 7;
    int n  = warp & 127;
    int bb = bw >> 8;
    int wi = bw & 255;
    int wd = wi >> 6, wh = (wi >> 3) & 7, ww = wi & 7;
    int td = n >> 6,  th = (n >> 3) & 7, tw = n & 7;
    int gd = (wd * 2 + td + 1) & 7;
    int gh = (wh * 8 + th + 4) & 63;
    int gw = (ww * 8 + tw + 4) & 63;
    long src = (((long)(bb * D_ + gd) * 64 + gh) * 64 + gw) * C_;

    float4 v = *(const float4*)(x + src + lane * 4);
    float s  = v.x + v.y + v.z + v.w;
    float sq = v.x * v.x + v.y * v.y + v.z * v.z + v.w * v.w;
#pragma unroll
    for (int o = 16; o > 0; o >>= 1) {
        s  += __shfl_xor_sync(0xffffffffu, s, o);
        sq += __shfl_xor_sync(0xffffffffu, sq, o);
    }
    float mean = s * (1.0f / C_);
    float var  = sq * (1.0f / C_) - mean * mean;
    float inv  = rsqrtf(var + 1e-5f);
    float4 gg = *(const float4*)(g + lane * 4);
    float4 bv = *(const float4*)(b + lane * 4);
    long o = (long)warp * C_ + lane * 4;
    *(half2*)(g_win + o)     = __floats2half2_rn((v.x - mean) * inv * gg.x + bv.x,
                                                 (v.y - mean) * inv * gg.y + bv.y);
    *(half2*)(g_win + o + 2) = __floats2half2_rn((v.z - mean) * inv * gg.z + bv.z,
                                                 (v.w - mean) * inv * gg.w + bv.w);
}

// ---------------- K2: relative position bias table (fp16, [h][query][key]) -------
__global__ void bias_kernel(const float* __restrict__ rpb) {
    int n = blockIdx.x;    // query
    int m = threadIdx.x;   // key
    int nd = n >> 6, nh = (n >> 3) & 7, nw = n & 7;
    int md = m >> 6, mh = (m >> 3) & 7, mw = m & 7;
    int rpi = (nd - md + 1) * 225 + (nh - mh + 7) * 15 + (nw - mw + 7);
#pragma unroll
    for (int h = 0; h < NH_; h++)
        g_biash[((long)h * NN_ + n) * NN_ + m] = __float2half(rpb[rpi * NH_ + h]);
}

// ---------------- K3: attention — 128 thr/CTA, CTA=(window,head,rowhalf) ---------
#define VPAD 136
__global__ void __launch_bounds__(128, 5) attn_kernel() {
    __shared__ half sVt[16 * VPAD];
    __shared__ int  lab[NN_];

    int bw = blockIdx.x >> 4;
    int h  = (blockIdx.x >> 1) & 7;
    int rh = blockIdx.x & 1;
    int tid = threadIdx.x, wid = tid >> 5, lane = tid & 31;
    int g = lane >> 2, t = lane & 3;
    long tokbase = (long)bw * 128;
    const half* Qp = g_qkvh + ((long)h * NTOK + tokbase) * 16;
    const half* Kp = g_qkvh + ((long)(8 + h) * NTOK + tokbase) * 16;
    const half* Vp = g_qkvh + ((long)(16 + h) * NTOK + tokbase) * 16;

    // stage V^T (dim-major): thread per token, 2 uint4 loads
    {
        int tok = tid;
        uint4 hv0 = *(const uint4*)(Vp + tok * 16);
        uint4 hv1 = *(const uint4*)(Vp + tok * 16 + 8);
        const half* h0 = (const half*)&hv0;
        const half* h1 = (const half*)&hv1;
#pragma unroll
        for (int d = 0; d < 8; d++) {
            sVt[d * VPAD + tok]       = h0[d];
            sVt[(8 + d) * VPAD + tok] = h1[d];
        }
    }
    {
        int wi = bw & 255;
        int sd = (wi >> 6) * 2 + (tid >> 6);
        int sh = ((wi >> 3) & 7) * 8 + ((tid >> 3) & 7);
        int sw = (wi & 7) * 8 + (tid & 7);
        int ld = sd < 6 ? 0 : (sd < 7 ? 1 : 2);
        int lh = sh < 56 ? 0 : (sh < 60 ? 1 : 2);
        int lw = sw < 56 ? 0 : (sw < 60 ? 1 : 2);
        lab[tid] = ld * 9 + lh * 3 + lw;
    }
    __syncthreads();

    // Q fragments (q pre-scaled by 0.25 in the QKV epilogue)
    int row0 = rh * 64 + wid * 16;
    uint32_t qf[4];
    qf[0] = *(const uint32_t*)(Qp + (row0 + g) * 16 + 2 * t);
    qf[1] = *(const uint32_t*)(Qp + (row0 + g + 8) * 16 + 2 * t);
    qf[2] = *(const uint32_t*)(Qp + (row0 + g) * 16 + 2 * t + 8);
    qf[3] = *(const uint32_t*)(Qp + (row0 + g + 8) * 16 + 2 * t + 8);

    // QK^T
    float acc[16][4];
#pragma unroll
    for (int j = 0; j < 16; j++) {
        uint32_t kf[2];
        kf[0] = *(const uint32_t*)(Kp + (8 * j + g) * 16 + 2 * t);
        kf[1] = *(const uint32_t*)(Kp + (8 * j + g) * 16 + 2 * t + 8);
        acc[j][0] = acc[j][1] = acc[j][2] = acc[j][3] = 0.0f;
        MMA(acc[j], qf, kf);
    }

    // bias (fp16) + mask + exp + row sums
    int myl_g  = lab[row0 + g];
    int myl_g8 = lab[row0 + g + 8];
    const half* bptr = g_biash + (long)h * NN_ * NN_;
    float sum_g = 0.0f, sum_g8 = 0.0f;
#pragma unroll
    for (int j = 0; j < 16; j++) {
        int col = 8 * j + 2 * t;
        float2 bg  = __half22float2(*(const half2*)(bptr + (row0 + g) * NN_ + col));
        float2 bg8 = __half22float2(*(const half2*)(bptr + (row0 + g + 8) * NN_ + col));
        int l0 = lab[col], l1 = lab[col + 1];
        float e0 = (l0 == myl_g)  ? __expf(acc[j][0] + bg.x)  : 0.0f;
        float e1 = (l1 == myl_g)  ? __expf(acc[j][1] + bg.y)  : 0.0f;
        float e2 = (l0 == myl_g8) ? __expf(acc[j][2] + bg8.x) : 0.0f;
        float e3 = (l1 == myl_g8) ? __expf(acc[j][3] + bg8.y) : 0.0f;
        acc[j][0] = e0; acc[j][1] = e1; acc[j][2] = e2; acc[j][3] = e3;
        sum_g += e0 + e1; sum_g8 += e2 + e3;
    }
    sum_g  += __shfl_xor_sync(0xffffffffu, sum_g, 1);
    sum_g  += __shfl_xor_sync(0xffffffffu, sum_g, 2);
    sum_g8 += __shfl_xor_sync(0xffffffffu, sum_g8, 1);
    sum_g8 += __shfl_xor_sync(0xffffffffu, sum_g8, 2);
    float rs_g = 1.0f / sum_g, rs_g8 = 1.0f / sum_g8;

    // P @ V (P fragments chained from acc)
    float oacc[2][4];
#pragma unroll
    for (int nj = 0; nj < 2; nj++)
#pragma unroll
        for (int c = 0; c < 4; c++) oacc[nj][c] = 0.0f;

#pragma unroll
    for (int kt = 0; kt < 8; kt++) {
        float* p0 = acc[2 * kt];
        float* p1 = acc[2 * kt + 1];
        uint32_t pf[4];
        pf[0] = packh2(p0[0], p0[1]);
        pf[1] = packh2(p0[2], p0[3]);
        pf[2] = packh2(p1[0], p1[1]);
        pf[3] = packh2(p1[2], p1[3]);
#pragma unroll
        for (int nj = 0; nj < 2; nj++) {
            int vb = (8 * nj + g) * VPAD + 16 * kt + 2 * t;
            uint32_t vf[2];
            vf[0] = *(const uint32_t*)&sVt[vb];
            vf[1] = *(const uint32_t*)&sVt[vb + 8];
            MMA(oacc[nj], pf, vf);
        }
    }

    // output: normalize, store fp16 row-major [tok][128]
    long og  = (tokbase + row0 + g) * 128 + h * 16;
    long og8 = og + 8 * 128;
#pragma unroll
    for (int nj = 0; nj < 2; nj++) {
        int dn = 8 * nj + 2 * t;
        *(half2*)(g_attn + og + dn)  = __floats2half2_rn(oacc[nj][0] * rs_g,
                                                         oacc[nj][1] * rs_g);
        *(half2*)(g_attn + og8 + dn) = __floats2half2_rn(oacc[nj][2] * rs_g8,
                                                         oacc[nj][3] * rs_g8);
    }
}

// -------- K6: window-reverse + roll + residual + LN2 (-> x1 f32, xn2 fp16) -------
__global__ void scatter_ln2_kernel(const float* __restrict__ x,
                                   const float* __restrict__ g2,
                                   const float* __restrict__ b2) {
    int tk = (blockIdx.x * blockDim.x + threadIdx.x) >> 5;
    int lane = threadIdx.x & 31;
    if (tk >= NTOK) return;
    int w = tk & 63, h = (tk >> 6) & 63, d = (tk >> 12) & 7, bb = tk >> 15;
    int sd = (d + 7) & 7;
    int sh = (h + 60) & 63;
    int sw = (w + 60) & 63;
    int bw = bb * 256 + (sd >> 1) * 64 + (sh >> 3) * 8 + (sw >> 3);
    int n  = (sd & 1) * 64 + (sh & 7) * 8 + (sw & 7);

    float4 xv = *(const float4*)(x + (long)tk * C_ + lane * 4);
    float4 pv = *(const float4*)(g_projout + ((long)bw * NN_ + n) * C_ + lane * 4);
    float4 s1;
    s1.x = xv.x + pv.x; s1.y = xv.y + pv.y;
    s1.z = xv.z + pv.z; s1.w = xv.w + pv.w;
    *(float4*)(g_x1 + (long)tk * C_ + lane * 4) = s1;

    float s  = s1.x + s1.y + s1.z + s1.w;
    float sq = s1.x * s1.x + s1.y * s1.y + s1.z * s1.z + s1.w * s1.w;
#pragma unroll
    for (int o = 16; o > 0; o >>= 1) {
        s  += __shfl_xor_sync(0xffffffffu, s, o);
        sq += __shfl_xor_sync(0xffffffffu, sq, o);
    }
    float mean = s * (1.0f / C_);
    float var  = sq * (1.0f / C_) - mean * mean;
    float inv  = rsqrtf(var + 1e-5f);
    float4 gg = *(const float4*)(g2 + lane * 4);
    float4 bv = *(const float4*)(b2 + lane * 4);
    long o = (long)tk * C_ + lane * 4;
    *(half2*)(g_xn2 + o)     = __floats2half2_rn((s1.x - mean) * inv * gg.x + bv.x,
                                                 (s1.y - mean) * inv * gg.y + bv.y);
    *(half2*)(g_xn2 + o + 2) = __floats2half2_rn((s1.z - mean) * inv * gg.z + bv.z,
                                                 (s1.w - mean) * inv * gg.w + bv.w);
}

// ---------------------------------------------------------------------------
extern "C" void kernel_launch(void* const* d_in, const int* in_sizes, int n_in,
                              void* d_out, int out_size) {
    const float* x      = (const float*)d_in[0];
    const float* qkv_w  = (const float*)d_in[1];
    const float* qkv_b  = (const float*)d_in[2];
    const float* proj_w = (const float*)d_in[3];
    const float* proj_b = (const float*)d_in[4];
    const float* rpb    = (const float*)d_in[5];
    const float* ln1_g  = (const float*)d_in[6];
    const float* ln1_b  = (const float*)d_in[7];
    const float* ln2_g  = (const float*)d_in[8];
    const float* ln2_b  = (const float*)d_in[9];
    const float* fc1_w  = (const float*)d_in[10];
    const float* fc1_b  = (const float*)d_in[11];
    const float* fc2_w  = (const float*)d_in[12];
    const float* fc2_b  = (const float*)d_in[13];
    float* out = (float*)d_out;

    half *p_win, *p_qkvh, *p_attn, *p_xn2, *p_hid;
    half *p_qkvw, *p_projw, *p_fc1w, *p_fc2w;
    float *p_projout, *p_x1;
    cudaGetSymbolAddress((void**)&p_win,     g_win);
    cudaGetSymbolAddress((void**)&p_qkvh,    g_qkvh);
    cudaGetSymbolAddress((void**)&p_attn,    g_attn);
    cudaGetSymbolAddress((void**)&p_xn2,     g_xn2);
    cudaGetSymbolAddress((void**)&p_hid,     g_hid);
    cudaGetSymbolAddress((void**)&p_qkvw,    g_qkvw);
    cudaGetSymbolAddress((void**)&p_projw,   g_projw);
    cudaGetSymbolAddress((void**)&p_fc1w,    g_fc1w);
    cudaGetSymbolAddress((void**)&p_fc2w,    g_fc2w);
    cudaGetSymbolAddress((void**)&p_projout, g_projout);
    cudaGetSymbolAddress((void**)&p_x1,      g_x1);

    const int SMEM = 4 * 128 * PADK * 2;   // 73728 B
    cudaFuncSetAttribute(mma_gemm<0, false, 2>, cudaFuncAttributeMaxDynamicSharedMemorySize, SMEM);
    cudaFuncSetAttribute(mma_gemm<0, false, 0>, cudaFuncAttributeMaxDynamicSharedMemorySize, SMEM);
    cudaFuncSetAttribute(mma_gemm<1, false, 1>, cudaFuncAttributeMaxDynamicSharedMemorySize, SMEM);
    cudaFuncSetAttribute(mma_gemm<0, true, 0>,  cudaFuncAttributeMaxDynamicSharedMemorySize, SMEM);

    // 0) weight convert + bias table
    convert_weights<<<256, 256>>>(qkv_w, proj_w, fc1_w, fc2_w);
    bias_kernel<<<128, 128>>>(rpb);

    // 1) LN1 + shift + partition
    ln_gather_kernel<<<8192, 256>>>(x, ln1_g, ln1_b);
    // 2) QKV GEMM -> head-major fp16 (q pre-scaled)
    mma_gemm<0, false, 2><<<dim3(3, 512), 256, SMEM>>>(
        p_win, p_qkvw, qkv_b, nullptr, nullptr, p_qkvh, 384, 128);
    // 3) attention (tensor cores, 128-thread CTAs)
    attn_kernel<<<NWIN * NH_ * 2, 128>>>();
    // 4) proj GEMM -> f32
    mma_gemm<0, false, 0><<<dim3(1, 512), 256, SMEM>>>(
        p_attn, p_projw, proj_b, nullptr, p_projout, nullptr, 128, 128);
    // 5) reverse + roll + residual + LN2
    scatter_ln2_kernel<<<8192, 256>>>(x, ln2_g, ln2_b);
    // 6) fc1 + GELU -> fp16
    mma_gemm<1, false, 1><<<dim3(4, 512), 256, SMEM>>>(
        p_xn2, p_fc1w, fc1_b, nullptr, nullptr, p_hid, 512, 128);
    // 7) fc2 + residual -> out (f32)
    mma_gemm<0, true, 0><<<dim3(1, 512), 256, SMEM>>>(
        p_hid, p_fc2w, fc2_b, p_x1, out, nullptr, 128, 512);
}

// round 13
// speedup vs baseline: 1.2345x; 1.0070x over previous
#include <cuda_runtime.h>
#include <cuda_fp16.h>
#include <math.h>
#include <stdint.h>

// Problem constants
#define B_    2
#define D_    8
#define C_    128
#define NH_   8
#define NTOK  65536
#define NWIN  512
#define NN_   128
#define MLPH  512

// ---------------- scratch (device globals) -----------------------------------
__device__ half  g_win[NTOK * C_];
__device__ half  g_qkvh[24LL * NTOK * 16];    // [part(3)][head(8)][tok][16]
__device__ half  g_biash[NH_ * NN_ * NN_];    // [h][n(query)][m(key)] fp16
__device__ half  g_attn[NTOK * C_];
__device__ float g_projout[NTOK * C_];
__device__ float g_x1[NTOK * C_];
__device__ half  g_xn2[NTOK * C_];
__device__ half  g_hid[(long)NTOK * MLPH];
// fp16 weights
__device__ half  g_qkvw[384 * C_];
__device__ half  g_projw[C_ * C_];
__device__ half  g_fc1w[MLPH * C_];
__device__ half  g_fc2w[C_ * MLPH];

__device__ __forceinline__ float gelu_exact(float x) {
    return 0.5f * x * (1.0f + erff(x * 0.70710678118654752f));
}

// ---- mma.sync m16n8k16 f16 -> f32 ------------------------------------------------
#define MMA(d, a, b)                                                            \
    asm volatile("mma.sync.aligned.m16n8k16.row.col.f32.f16.f16.f32 "           \
        "{%0,%1,%2,%3}, {%4,%5,%6,%7}, {%8,%9}, {%0,%1,%2,%3};"                 \
        : "+f"((d)[0]), "+f"((d)[1]), "+f"((d)[2]), "+f"((d)[3])                \
        : "r"((a)[0]), "r"((a)[1]), "r"((a)[2]), "r"((a)[3]),                    \
          "r"((b)[0]), "r"((b)[1]))

#define LDMX4(r, addr)                                                          \
    asm volatile("ldmatrix.sync.aligned.m8n8.x4.shared.b16 {%0,%1,%2,%3}, [%4];"\
        : "=r"((r)[0]), "=r"((r)[1]), "=r"((r)[2]), "=r"((r)[3]) : "r"(addr))
#define LDMX2(r, addr)                                                          \
    asm volatile("ldmatrix.sync.aligned.m8n8.x2.shared.b16 {%0,%1}, [%2];"      \
        : "=r"((r)[0]), "=r"((r)[1]) : "r"(addr))

__device__ __forceinline__ uint32_t packh2(float v0, float v1) {
    half2 h = __floats2half2_rn(v0, v1);
    return *(uint32_t*)&h;
}
__device__ __forceinline__ uint32_t smem_u32(const void* p) {
    uint32_t a;
    asm("{ .reg .u64 t; cvta.to.shared.u64 t, %1; cvt.u32.u64 %0, t; }" : "=r"(a) : "l"(p));
    return a;
}
__device__ __forceinline__ void cpa16(uint32_t d, const void* s) {
    asm volatile("cp.async.cg.shared.global [%0], [%1], 16;" :: "r"(d), "l"(s));
}
#define CP_COMMIT() asm volatile("cp.async.commit_group;" ::: "memory")
#define CP_WAIT0()  asm volatile("cp.async.wait_group 0;" ::: "memory")
#define CP_WAIT1()  asm volatile("cp.async.wait_group 1;" ::: "memory")

// ==================  GEMM: BM=128 BN=64 BK=64, 256 thr, 3 CTAs/SM  ================
#define PADK 72
#define BUFA (128 * PADK * 2)     // bytes per A stage
#define BUFW (64 * PADK * 2)      // bytes per W stage

template <int ACT, bool RES, int OMODE>
__global__ void __launch_bounds__(256, 3)
mma_gemm(const half* __restrict__ A, const half* __restrict__ W,
         const float* __restrict__ bias, const float* __restrict__ res,
         float* __restrict__ Cf, half* __restrict__ Chf,
         int N, int K) {
    extern __shared__ half smem[];
    half* sA = smem;                       // 2 stages of 128 x PADK
    half* sW = smem + 2 * 128 * PADK;      // 2 stages of 64 x PADK
    uint32_t sAu = smem_u32(sA), sWu = smem_u32(sW);

    int tid = threadIdx.x, wid = tid >> 5, lane = tid & 31;
    int g = lane >> 2, t = lane & 3;
    int m0 = blockIdx.y * 128, n0 = blockIdx.x * 64;
    int wm = (wid >> 1) * 32, wn = (wid & 1) * 32;   // warp tile 32m x 32n

    float acc[2][4][4];
#pragma unroll
    for (int i = 0; i < 2; i++)
#pragma unroll
        for (int j = 0; j < 4; j++)
#pragma unroll
            for (int c = 0; c < 4; c++) acc[i][j][c] = 0.0f;

    int crow = tid >> 3, cseg = (tid & 7) * 8;
    auto issue = [&](int kc, int buf) {
#pragma unroll
        for (int i = 0; i < 4; i++) {
            int row = crow + i * 32;
            cpa16(sAu + (uint32_t)buf * BUFA + (row * PADK + cseg) * 2,
                  A + (long)(m0 + row) * K + kc + cseg);
        }
#pragma unroll
        for (int i = 0; i < 2; i++) {
            int row = crow + i * 32;
            cpa16(sWu + (uint32_t)buf * BUFW + (row * PADK + cseg) * 2,
                  W + (long)(n0 + row) * K + kc + cseg);
        }
        CP_COMMIT();
    };

    int lrow = lane & 7, lsel = lane >> 3;
    uint32_t aBase = sAu + ((wm + (lsel & 1) * 8 + lrow) * PADK + (lsel >> 1) * 8) * 2;
    uint32_t bBase = sWu + ((wn + lrow) * PADK + (lsel & 1) * 8) * 2;

    int nch = K >> 6;
    issue(0, 0);
    for (int c = 0; c < nch; c++) {
        if (c + 1 < nch) { issue((c + 1) << 6, (c + 1) & 1); CP_WAIT1(); }
        else             { CP_WAIT0(); }
        __syncthreads();
        uint32_t aofs = (uint32_t)(c & 1) * BUFA;
        uint32_t wofs = (uint32_t)(c & 1) * BUFW;
#pragma unroll
        for (int ks = 0; ks < 4; ks++) {
            uint32_t kb2 = ks * 32;
            uint32_t fa[2][4], fb[4][2];
#pragma unroll
            for (int mi = 0; mi < 2; mi++)
                LDMX4(fa[mi], aBase + aofs + mi * (16 * PADK * 2) + kb2);
#pragma unroll
            for (int nj = 0; nj < 4; nj++)
                LDMX2(fb[nj], bBase + wofs + nj * (8 * PADK * 2) + kb2);
#pragma unroll
            for (int mi = 0; mi < 2; mi++)
#pragma unroll
                for (int nj = 0; nj < 4; nj++)
                    MMA(acc[mi][nj], fa[mi], fb[nj]);
        }
        __syncthreads();
    }

#pragma unroll
    for (int mi = 0; mi < 2; mi++) {
#pragma unroll
        for (int cr = 0; cr < 2; cr++) {
            int m = m0 + wm + mi * 16 + g + cr * 8;
#pragma unroll
            for (int nj = 0; nj < 4; nj++) {
                int n = n0 + wn + nj * 8 + 2 * t;
                float2 bb = *(const float2*)(bias + n);
                float v0 = acc[mi][nj][cr * 2 + 0] + bb.x;
                float v1 = acc[mi][nj][cr * 2 + 1] + bb.y;
                if (OMODE == 2 && n < 128) { v0 *= 0.25f; v1 *= 0.25f; }
                if (ACT == 1) { v0 = gelu_exact(v0); v1 = gelu_exact(v1); }
                if (RES) {
                    float2 r = *(const float2*)(res + (long)m * N + n);
                    v0 += r.x; v1 += r.y;
                }
                if (OMODE == 2) {
                    int p = n >> 7, hh = (n >> 4) & 7, d = n & 15;
                    long addr = ((long)(p * 8 + hh) * NTOK + m) * 16 + d;
                    *(half2*)(Chf + addr) = __floats2half2_rn(v0, v1);
                } else if (OMODE == 1) {
                    *(half2*)(Chf + (long)m * N + n) = __floats2half2_rn(v0, v1);
                } else {
                    float2 o; o.x = v0; o.y = v1;
                    *(float2*)(Cf + (long)m * N + n) = o;
                }
            }
        }
    }
}

// ---------------- weight convert ------------------------------------------------
__global__ void convert_weights(const float* __restrict__ qkv_w,
                                const float* __restrict__ proj_w,
                                const float* __restrict__ fc1_w,
                                const float* __restrict__ fc2_w) {
    int i = blockIdx.x * blockDim.x + threadIdx.x;
    if (i < 49152) g_qkvw[i] = __float2half(qkv_w[i]);
    if (i < 16384) g_projw[i] = __float2half(proj_w[i]);
    g_fc1w[i] = __float2half(fc1_w[i]);
    g_fc2w[i] = __float2half(fc2_w[i]);
}

// ---------------- K1: LN1 + cyclic shift + window partition (-> fp16) ------------
__global__ void ln_gather_kernel(const float* __restrict__ x,
                                 const float* __restrict__ g,
                                 const float* __restrict__ b) {
    int warp = (blockIdx.x * blockDim.x + threadIdx.x) >> 5;
    int lane = threadIdx.x & 31;
    if (warp >= NWIN * NN_) return;
    int bw = warp >> 7;
    int n  = warp & 127;
    int bb = bw >> 8;
    int wi = bw & 255;
    int wd = wi >> 6, wh = (wi >> 3) & 7, ww = wi & 7;
    int td = n >> 6,  th = (n >> 3) & 7, tw = n & 7;
    int gd = (wd * 2 + td + 1) & 7;
    int gh = (wh * 8 + th + 4) & 63;
    int gw = (ww * 8 + tw + 4) & 63;
    long src = (((long)(bb * D_ + gd) * 64 + gh) * 64 + gw) * C_;

    float4 v = *(const float4*)(x + src + lane * 4);
    float s  = v.x + v.y + v.z + v.w;
    float sq = v.x * v.x + v.y * v.y + v.z * v.z + v.w * v.w;
#pragma unroll
    for (int o = 16; o > 0; o >>= 1) {
        s  += __shfl_xor_sync(0xffffffffu, s, o);
        sq += __shfl_xor_sync(0xffffffffu, sq, o);
    }
    float mean = s * (1.0f / C_);
    float var  = sq * (1.0f / C_) - mean * mean;
    float inv  = rsqrtf(var + 1e-5f);
    float4 gg = *(const float4*)(g + lane * 4);
    float4 bv = *(const float4*)(b + lane * 4);
    long o = (long)warp * C_ + lane * 4;
    *(half2*)(g_win + o)     = __floats2half2_rn((v.x - mean) * inv * gg.x + bv.x,
                                                 (v.y - mean) * inv * gg.y + bv.y);
    *(half2*)(g_win + o + 2) = __floats2half2_rn((v.z - mean) * inv * gg.z + bv.z,
                                                 (v.w - mean) * inv * gg.w + bv.w);
}

// ---------------- K2: relative position bias table (fp16) ------------------------
__global__ void bias_kernel(const float* __restrict__ rpb) {
    int n = blockIdx.x;    // query
    int m = threadIdx.x;   // key
    int nd = n >> 6, nh = (n >> 3) & 7, nw = n & 7;
    int md = m >> 6, mh = (m >> 3) & 7, mw = m & 7;
    int rpi = (nd - md + 1) * 225 + (nh - mh + 7) * 15 + (nw - mw + 7);
#pragma unroll
    for (int h = 0; h < NH_; h++)
        g_biash[((long)h * NN_ + n) * NN_ + m] = __float2half(rpb[rpi * NH_ + h]);
}

// ---------------- K3: attention — 128 thr/CTA, K and V staged in smem ------------
#define VPAD 136
__global__ void __launch_bounds__(128, 5) attn_kernel() {
    __shared__ half sVt[16 * VPAD];
    __shared__ half sK[128 * 16];
    __shared__ int  lab[NN_];

    int bw = blockIdx.x >> 4;
    int h  = (blockIdx.x >> 1) & 7;
    int rh = blockIdx.x & 1;
    int tid = threadIdx.x, wid = tid >> 5, lane = tid & 31;
    int g = lane >> 2, t = lane & 3;
    long tokbase = (long)bw * 128;
    const half* Qp = g_qkvh + ((long)h * NTOK + tokbase) * 16;
    const half* Kp = g_qkvh + ((long)(8 + h) * NTOK + tokbase) * 16;
    const half* Vp = g_qkvh + ((long)(16 + h) * NTOK + tokbase) * 16;

    // stage K (linear) and V^T (dim-major) into smem — coalesced
    {
        int tok = tid;
        uint4 kv0 = *(const uint4*)(Kp + tok * 16);
        uint4 kv1 = *(const uint4*)(Kp + tok * 16 + 8);
        *(uint4*)&sK[tok * 16]     = kv0;
        *(uint4*)&sK[tok * 16 + 8] = kv1;
        uint4 hv0 = *(const uint4*)(Vp + tok * 16);
        uint4 hv1 = *(const uint4*)(Vp + tok * 16 + 8);
        const half* h0 = (const half*)&hv0;
        const half* h1 = (const half*)&hv1;
#pragma unroll
        for (int d = 0; d < 8; d++) {
            sVt[d * VPAD + tok]       = h0[d];
            sVt[(8 + d) * VPAD + tok] = h1[d];
        }
    }
    {
        int wi = bw & 255;
        int sd = (wi >> 6) * 2 + (tid >> 6);
        int sh = ((wi >> 3) & 7) * 8 + ((tid >> 3) & 7);
        int sw = (wi & 7) * 8 + (tid & 7);
        int ld = sd < 6 ? 0 : (sd < 7 ? 1 : 2);
        int lh = sh < 56 ? 0 : (sh < 60 ? 1 : 2);
        int lw = sw < 56 ? 0 : (sw < 60 ? 1 : 2);
        lab[tid] = ld * 9 + lh * 3 + lw;
    }
    __syncthreads();

    // Q fragments (q pre-scaled by 0.25 in the QKV epilogue)
    int row0 = rh * 64 + wid * 16;
    uint32_t qf[4];
    qf[0] = *(const uint32_t*)(Qp + (row0 + g) * 16 + 2 * t);
    qf[1] = *(const uint32_t*)(Qp + (row0 + g + 8) * 16 + 2 * t);
    qf[2] = *(const uint32_t*)(Qp + (row0 + g) * 16 + 2 * t + 8);
    qf[3] = *(const uint32_t*)(Qp + (row0 + g + 8) * 16 + 2 * t + 8);

    // QK^T from smem K
    float acc[16][4];
#pragma unroll
    for (int j = 0; j < 16; j++) {
        uint32_t kf[2];
        kf[0] = *(const uint32_t*)&sK[(8 * j + g) * 16 + 2 * t];
        kf[1] = *(const uint32_t*)&sK[(8 * j + g) * 16 + 2 * t + 8];
        acc[j][0] = acc[j][1] = acc[j][2] = acc[j][3] = 0.0f;
        MMA(acc[j], qf, kf);
    }

    // bias (fp16) + mask + exp + row sums
    int myl_g  = lab[row0 + g];
    int myl_g8 = lab[row0 + g + 8];
    const half* bptr = g_biash + (long)h * NN_ * NN_;
    float sum_g = 0.0f, sum_g8 = 0.0f;
#pragma unroll
    for (int j = 0; j < 16; j++) {
        int col = 8 * j + 2 * t;
        float2 bg  = __half22float2(*(const half2*)(bptr + (row0 + g) * NN_ + col));
        float2 bg8 = __half22float2(*(const half2*)(bptr + (row0 + g + 8) * NN_ + col));
        int l0 = lab[col], l1 = lab[col + 1];
        float e0 = (l0 == myl_g)  ? __expf(acc[j][0] + bg.x)  : 0.0f;
        float e1 = (l1 == myl_g)  ? __expf(acc[j][1] + bg.y)  : 0.0f;
        float e2 = (l0 == myl_g8) ? __expf(acc[j][2] + bg8.x) : 0.0f;
        float e3 = (l1 == myl_g8) ? __expf(acc[j][3] + bg8.y) : 0.0f;
        acc[j][0] = e0; acc[j][1] = e1; acc[j][2] = e2; acc[j][3] = e3;
        sum_g += e0 + e1; sum_g8 += e2 + e3;
    }
    sum_g  += __shfl_xor_sync(0xffffffffu, sum_g, 1);
    sum_g  += __shfl_xor_sync(0xffffffffu, sum_g, 2);
    sum_g8 += __shfl_xor_sync(0xffffffffu, sum_g8, 1);
    sum_g8 += __shfl_xor_sync(0xffffffffu, sum_g8, 2);
    float rs_g = 1.0f / sum_g, rs_g8 = 1.0f / sum_g8;

    // P @ V
    float oacc[2][4];
#pragma unroll
    for (int nj = 0; nj < 2; nj++)
#pragma unroll
        for (int c = 0; c < 4; c++) oacc[nj][c] = 0.0f;

#pragma unroll
    for (int kt = 0; kt < 8; kt++) {
        float* p0 = acc[2 * kt];
        float* p1 = acc[2 * kt + 1];
        uint32_t pf[4];
        pf[0] = packh2(p0[0], p0[1]);
        pf[1] = packh2(p0[2], p0[3]);
        pf[2] = packh2(p1[0], p1[1]);
        pf[3] = packh2(p1[2], p1[3]);
#pragma unroll
        for (int nj = 0; nj < 2; nj++) {
            int vb = (8 * nj + g) * VPAD + 16 * kt + 2 * t;
            uint32_t vf[2];
            vf[0] = *(const uint32_t*)&sVt[vb];
            vf[1] = *(const uint32_t*)&sVt[vb + 8];
            MMA(oacc[nj], pf, vf);
        }
    }

    long og  = (tokbase + row0 + g) * 128 + h * 16;
    long og8 = og + 8 * 128;
#pragma unroll
    for (int nj = 0; nj < 2; nj++) {
        int dn = 8 * nj + 2 * t;
        *(half2*)(g_attn + og + dn)  = __floats2half2_rn(oacc[nj][0] * rs_g,
                                                         oacc[nj][1] * rs_g);
        *(half2*)(g_attn + og8 + dn) = __floats2half2_rn(oacc[nj][2] * rs_g8,
                                                         oacc[nj][3] * rs_g8);
    }
}

// -------- K6: window-reverse + roll + residual + LN2 (-> x1 f32, xn2 fp16) -------
__global__ void scatter_ln2_kernel(const float* __restrict__ x,
                                   const float* __restrict__ g2,
                                   const float* __restrict__ b2) {
    int tk = (blockIdx.x * blockDim.x + threadIdx.x) >> 5;
    int lane = threadIdx.x & 31;
    if (tk >= NTOK) return;
    int w = tk & 63, h = (tk >> 6) & 63, d = (tk >> 12) & 7, bb = tk >> 15;
    int sd = (d + 7) & 7;
    int sh = (h + 60) & 63;
    int sw = (w + 60) & 63;
    int bw = bb * 256 + (sd >> 1) * 64 + (sh >> 3) * 8 + (sw >> 3);
    int n  = (sd & 1) * 64 + (sh & 7) * 8 + (sw & 7);

    float4 xv = *(const float4*)(x + (long)tk * C_ + lane * 4);
    float4 pv = *(const float4*)(g_projout + ((long)bw * NN_ + n) * C_ + lane * 4);
    float4 s1;
    s1.x = xv.x + pv.x; s1.y = xv.y + pv.y;
    s1.z = xv.z + pv.z; s1.w = xv.w + pv.w;
    *(float4*)(g_x1 + (long)tk * C_ + lane * 4) = s1;

    float s  = s1.x + s1.y + s1.z + s1.w;
    float sq = s1.x * s1.x + s1.y * s1.y + s1.z * s1.z + s1.w * s1.w;
#pragma unroll
    for (int o = 16; o > 0; o >>= 1) {
        s  += __shfl_xor_sync(0xffffffffu, s, o);
        sq += __shfl_xor_sync(0xffffffffu, sq, o);
    }
    float mean = s * (1.0f / C_);
    float var  = sq * (1.0f / C_) - mean * mean;
    float inv  = rsqrtf(var + 1e-5f);
    float4 gg = *(const float4*)(g2 + lane * 4);
    float4 bv = *(const float4*)(b2 + lane * 4);
    long o = (long)tk * C_ + lane * 4;
    *(half2*)(g_xn2 + o)     = __floats2half2_rn((s1.x - mean) * inv * gg.x + bv.x,
                                                 (s1.y - mean) * inv * gg.y + bv.y);
    *(half2*)(g_xn2 + o + 2) = __floats2half2_rn((s1.z - mean) * inv * gg.z + bv.z,
                                                 (s1.w - mean) * inv * gg.w + bv.w);
}

// ---------------------------------------------------------------------------
extern "C" void kernel_launch(void* const* d_in, const int* in_sizes, int n_in,
                              void* d_out, int out_size) {
    const float* x      = (const float*)d_in[0];
    const float* qkv_w  = (const float*)d_in[1];
    const float* qkv_b  = (const float*)d_in[2];
    const float* proj_w = (const float*)d_in[3];
    const float* proj_b = (const float*)d_in[4];
    const float* rpb    = (const float*)d_in[5];
    const float* ln1_g  = (const float*)d_in[6];
    const float* ln1_b  = (const float*)d_in[7];
    const float* ln2_g  = (const float*)d_in[8];
    const float* ln2_b  = (const float*)d_in[9];
    const float* fc1_w  = (const float*)d_in[10];
    const float* fc1_b  = (const float*)d_in[11];
    const float* fc2_w  = (const float*)d_in[12];
    const float* fc2_b  = (const float*)d_in[13];
    float* out = (float*)d_out;

    half *p_win, *p_qkvh, *p_attn, *p_xn2, *p_hid;
    half *p_qkvw, *p_projw, *p_fc1w, *p_fc2w;
    float *p_projout, *p_x1;
    cudaGetSymbolAddress((void**)&p_win,     g_win);
    cudaGetSymbolAddress((void**)&p_qkvh,    g_qkvh);
    cudaGetSymbolAddress((void**)&p_attn,    g_attn);
    cudaGetSymbolAddress((void**)&p_xn2,     g_xn2);
    cudaGetSymbolAddress((void**)&p_hid,     g_hid);
    cudaGetSymbolAddress((void**)&p_qkvw,    g_qkvw);
    cudaGetSymbolAddress((void**)&p_projw,   g_projw);
    cudaGetSymbolAddress((void**)&p_fc1w,    g_fc1w);
    cudaGetSymbolAddress((void**)&p_fc2w,    g_fc2w);
    cudaGetSymbolAddress((void**)&p_projout, g_projout);
    cudaGetSymbolAddress((void**)&p_x1,      g_x1);

    const int SMEM = 2 * (128 + 64) * PADK * 2;   // 55296 B
    cudaFuncSetAttribute(mma_gemm<0, false, 2>, cudaFuncAttributeMaxDynamicSharedMemorySize, SMEM);
    cudaFuncSetAttribute(mma_gemm<0, false, 0>, cudaFuncAttributeMaxDynamicSharedMemorySize, SMEM);
    cudaFuncSetAttribute(mma_gemm<1, false, 1>, cudaFuncAttributeMaxDynamicSharedMemorySize, SMEM);
    cudaFuncSetAttribute(mma_gemm<0, true, 0>,  cudaFuncAttributeMaxDynamicSharedMemorySize, SMEM);

    // 0) weight convert + bias table
    convert_weights<<<256, 256>>>(qkv_w, proj_w, fc1_w, fc2_w);
    bias_kernel<<<128, 128>>>(rpb);

    // 1) LN1 + shift + partition
    ln_gather_kernel<<<8192, 256>>>(x, ln1_g, ln1_b);
    // 2) QKV GEMM -> head-major fp16 (q pre-scaled)
    mma_gemm<0, false, 2><<<dim3(6, 512), 256, SMEM>>>(
        p_win, p_qkvw, qkv_b, nullptr, nullptr, p_qkvh, 384, 128);
    // 3) attention
    attn_kernel<<<NWIN * NH_ * 2, 128>>>();
    // 4) proj GEMM -> f32
    mma_gemm<0, false, 0><<<dim3(2, 512), 256, SMEM>>>(
        p_attn, p_projw, proj_b, nullptr, p_projout, nullptr, 128, 128);
    // 5) reverse + roll + residual + LN2
    scatter_ln2_kernel<<<8192, 256>>>(x, ln2_g, ln2_b);
    // 6) fc1 + GELU -> fp16
    mma_gemm<1, false, 1><<<dim3(8, 512), 256, SMEM>>>(
        p_xn2, p_fc1w, fc1_b, nullptr, nullptr, p_hid, 512, 128);
    // 7) fc2 + residual -> out (f32)
    mma_gemm<0, true, 0><<<dim3(2, 512), 256, SMEM>>>(
        p_hid, p_fc2w, fc2_b, p_x1, out, nullptr, 128, 512);
}

// round 14
// speedup vs baseline: 1.2453x; 1.0088x over previous
#include <cuda_runtime.h>
#include <cuda_fp16.h>
#include <math.h>
#include <stdint.h>

// Problem constants
#define B_    2
#define D_    8
#define C_    128
#define NH_   8
#define NTOK  65536
#define NWIN  512
#define NN_   128
#define MLPH  512

// ---------------- scratch (device globals) -----------------------------------
__device__ half  g_win[NTOK * C_];
__device__ half  g_qkvh[24LL * NTOK * 16];    // [part(3)][head(8)][tok][16]
__device__ half  g_tbl[8LL * NH_ * NN_ * NN_]; // [class][h][n][m] bias+mask fp16
__device__ half  g_attn[NTOK * C_];
__device__ half  g_projout_h[NTOK * C_];
__device__ float g_x1[NTOK * C_];
__device__ half  g_xn2[NTOK * C_];
__device__ half  g_hid[(long)NTOK * MLPH];
// fp16 weights
__device__ half  g_qkvw[384 * C_];
__device__ half  g_projw[C_ * C_];
__device__ half  g_fc1w[MLPH * C_];
__device__ half  g_fc2w[C_ * MLPH];

__device__ __forceinline__ float gelu_exact(float x) {
    return 0.5f * x * (1.0f + erff(x * 0.70710678118654752f));
}

// ---- mma.sync m16n8k16 f16 -> f32 ------------------------------------------------
#define MMA(d, a, b)                                                            \
    asm volatile("mma.sync.aligned.m16n8k16.row.col.f32.f16.f16.f32 "           \
        "{%0,%1,%2,%3}, {%4,%5,%6,%7}, {%8,%9}, {%0,%1,%2,%3};"                 \
        : "+f"((d)[0]), "+f"((d)[1]), "+f"((d)[2]), "+f"((d)[3])                \
        : "r"((a)[0]), "r"((a)[1]), "r"((a)[2]), "r"((a)[3]),                    \
          "r"((b)[0]), "r"((b)[1]))

#define LDMX4(r, addr)                                                          \
    asm volatile("ldmatrix.sync.aligned.m8n8.x4.shared.b16 {%0,%1,%2,%3}, [%4];"\
        : "=r"((r)[0]), "=r"((r)[1]), "=r"((r)[2]), "=r"((r)[3]) : "r"(addr))
#define LDMX2(r, addr)                                                          \
    asm volatile("ldmatrix.sync.aligned.m8n8.x2.shared.b16 {%0,%1}, [%2];"      \
        : "=r"((r)[0]), "=r"((r)[1]) : "r"(addr))

__device__ __forceinline__ uint32_t packh2(float v0, float v1) {
    half2 h = __floats2half2_rn(v0, v1);
    return *(uint32_t*)&h;
}
__device__ __forceinline__ uint32_t smem_u32(const void* p) {
    uint32_t a;
    asm("{ .reg .u64 t; cvta.to.shared.u64 t, %1; cvt.u32.u64 %0, t; }" : "=r"(a) : "l"(p));
    return a;
}
__device__ __forceinline__ void cpa16(uint32_t d, const void* s) {
    asm volatile("cp.async.cg.shared.global [%0], [%1], 16;" :: "r"(d), "l"(s));
}
#define CP_COMMIT() asm volatile("cp.async.commit_group;" ::: "memory")
#define CP_WAIT0()  asm volatile("cp.async.wait_group 0;" ::: "memory")
#define CP_WAIT1()  asm volatile("cp.async.wait_group 1;" ::: "memory")

// ==================  GEMM: BM=128 BN=64 BK=64, 256 thr, 3 CTAs/SM  ================
#define PADK 72
#define BUFA (128 * PADK * 2)
#define BUFW (64 * PADK * 2)

template <int ACT, bool RES, int OMODE>
__global__ void __launch_bounds__(256, 3)
mma_gemm(const half* __restrict__ A, const half* __restrict__ W,
         const float* __restrict__ bias, const float* __restrict__ res,
         float* __restrict__ Cf, half* __restrict__ Chf,
         int N, int K) {
    extern __shared__ half smem[];
    half* sA = smem;
    half* sW = smem + 2 * 128 * PADK;
    uint32_t sAu = smem_u32(sA), sWu = smem_u32(sW);

    int tid = threadIdx.x, wid = tid >> 5, lane = tid & 31;
    int g = lane >> 2, t = lane & 3;
    int m0 = blockIdx.y * 128, n0 = blockIdx.x * 64;
    int wm = (wid >> 1) * 32, wn = (wid & 1) * 32;

    float acc[2][4][4];
#pragma unroll
    for (int i = 0; i < 2; i++)
#pragma unroll
        for (int j = 0; j < 4; j++)
#pragma unroll
            for (int c = 0; c < 4; c++) acc[i][j][c] = 0.0f;

    int crow = tid >> 3, cseg = (tid & 7) * 8;
    auto issue = [&](int kc, int buf) {
#pragma unroll
        for (int i = 0; i < 4; i++) {
            int row = crow + i * 32;
            cpa16(sAu + (uint32_t)buf * BUFA + (row * PADK + cseg) * 2,
                  A + (long)(m0 + row) * K + kc + cseg);
        }
#pragma unroll
        for (int i = 0; i < 2; i++) {
            int row = crow + i * 32;
            cpa16(sWu + (uint32_t)buf * BUFW + (row * PADK + cseg) * 2,
                  W + (long)(n0 + row) * K + kc + cseg);
        }
        CP_COMMIT();
    };

    int lrow = lane & 7, lsel = lane >> 3;
    uint32_t aBase = sAu + ((wm + (lsel & 1) * 8 + lrow) * PADK + (lsel >> 1) * 8) * 2;
    uint32_t bBase = sWu + ((wn + lrow) * PADK + (lsel & 1) * 8) * 2;

    int nch = K >> 6;
    issue(0, 0);
    for (int c = 0; c < nch; c++) {
        if (c + 1 < nch) { issue((c + 1) << 6, (c + 1) & 1); CP_WAIT1(); }
        else             { CP_WAIT0(); }
        __syncthreads();
        uint32_t aofs = (uint32_t)(c & 1) * BUFA;
        uint32_t wofs = (uint32_t)(c & 1) * BUFW;
#pragma unroll
        for (int ks = 0; ks < 4; ks++) {
            uint32_t kb2 = ks * 32;
            uint32_t fa[2][4], fb[4][2];
#pragma unroll
            for (int mi = 0; mi < 2; mi++)
                LDMX4(fa[mi], aBase + aofs + mi * (16 * PADK * 2) + kb2);
#pragma unroll
            for (int nj = 0; nj < 4; nj++)
                LDMX2(fb[nj], bBase + wofs + nj * (8 * PADK * 2) + kb2);
#pragma unroll
            for (int mi = 0; mi < 2; mi++)
#pragma unroll
                for (int nj = 0; nj < 4; nj++)
                    MMA(acc[mi][nj], fa[mi], fb[nj]);
        }
        __syncthreads();
    }

#pragma unroll
    for (int mi = 0; mi < 2; mi++) {
#pragma unroll
        for (int cr = 0; cr < 2; cr++) {
            int m = m0 + wm + mi * 16 + g + cr * 8;
#pragma unroll
            for (int nj = 0; nj < 4; nj++) {
                int n = n0 + wn + nj * 8 + 2 * t;
                float2 bb = *(const float2*)(bias + n);
                float v0 = acc[mi][nj][cr * 2 + 0] + bb.x;
                float v1 = acc[mi][nj][cr * 2 + 1] + bb.y;
                if (OMODE == 2 && n < 128) { v0 *= 0.25f; v1 *= 0.25f; }
                if (ACT == 1) { v0 = gelu_exact(v0); v1 = gelu_exact(v1); }
                if (RES) {
                    float2 r = *(const float2*)(res + (long)m * N + n);
                    v0 += r.x; v1 += r.y;
                }
                if (OMODE == 2) {
                    int p = n >> 7, hh = (n >> 4) & 7, d = n & 15;
                    long addr = ((long)(p * 8 + hh) * NTOK + m) * 16 + d;
                    *(half2*)(Chf + addr) = __floats2half2_rn(v0, v1);
                } else if (OMODE == 1) {
                    *(half2*)(Chf + (long)m * N + n) = __floats2half2_rn(v0, v1);
                } else {
                    float2 o; o.x = v0; o.y = v1;
                    *(float2*)(Cf + (long)m * N + n) = o;
                }
            }
        }
    }
}

// ---------------- weight convert ------------------------------------------------
__global__ void convert_weights(const float* __restrict__ qkv_w,
                                const float* __restrict__ proj_w,
                                const float* __restrict__ fc1_w,
                                const float* __restrict__ fc2_w) {
    int i = blockIdx.x * blockDim.x + threadIdx.x;
    if (i < 49152) g_qkvw[i] = __float2half(qkv_w[i]);
    if (i < 16384) g_projw[i] = __float2half(proj_w[i]);
    g_fc1w[i] = __float2half(fc1_w[i]);
    g_fc2w[i] = __float2half(fc2_w[i]);
}

// ---------------- K1: LN1 + cyclic shift + window partition (-> fp16) ------------
__global__ void ln_gather_kernel(const float* __restrict__ x,
                                 const float* __restrict__ g,
                                 const float* __restrict__ b) {
    int warp = (blockIdx.x * blockDim.x + threadIdx.x) >> 5;
    int lane = threadIdx.x & 31;
    if (warp >= NWIN * NN_) return;
    int bw = warp >> 7;
    int n  = warp & 127;
    int bb = bw >> 8;
    int wi = bw & 255;
    int wd = wi >> 6, wh = (wi >> 3) & 7, ww = wi & 7;
    int td = n >> 6,  th = (n >> 3) & 7, tw = n & 7;
    int gd = (wd * 2 + td + 1) & 7;
    int gh = (wh * 8 + th + 4) & 63;
    int gw = (ww * 8 + tw + 4) & 63;
    long src = (((long)(bb * D_ + gd) * 64 + gh) * 64 + gw) * C_;

    float4 v = *(const float4*)(x + src + lane * 4);
    float s  = v.x + v.y + v.z + v.w;
    float sq = v.x * v.x + v.y * v.y + v.z * v.z + v.w * v.w;
#pragma unroll
    for (int o = 16; o > 0; o >>= 1) {
        s  += __shfl_xor_sync(0xffffffffu, s, o);
        sq += __shfl_xor_sync(0xffffffffu, sq, o);
    }
    float mean = s * (1.0f / C_);
    float var  = sq * (1.0f / C_) - mean * mean;
    float inv  = rsqrtf(var + 1e-5f);
    float4 gg = *(const float4*)(g + lane * 4);
    float4 bv = *(const float4*)(b + lane * 4);
    long o = (long)warp * C_ + lane * 4;
    *(half2*)(g_win + o)     = __floats2half2_rn((v.x - mean) * inv * gg.x + bv.x,
                                                 (v.y - mean) * inv * gg.y + bv.y);
    *(half2*)(g_win + o + 2) = __floats2half2_rn((v.z - mean) * inv * gg.z + bv.z,
                                                 (v.w - mean) * inv * gg.w + bv.w);
}

// ---------------- K2: bias+mask table (fp16, [class][h][n][m]) --------------------
// class bits: 4 = d-boundary window (wd==3), 2 = h-boundary (wh==7), 1 = w-boundary
__global__ void bias_kernel(const float* __restrict__ rpb) {
    int n = blockIdx.x;    // query
    int m = threadIdx.x;   // key
    int tdn = n >> 6, thn = (n >> 3) & 7, twn = n & 7;
    int tdm = m >> 6, thm = (m >> 3) & 7, twm = m & 7;
    int rpi = (tdn - tdm + 1) * 225 + (thn - thm + 7) * 15 + (twn - twm + 7);
    bool dd = tdn != tdm;
    bool dh = (thn < 4) != (thm < 4);
    bool dw = (twn < 4) != (twm < 4);
#pragma unroll
    for (int h = 0; h < NH_; h++) {
        float bias = rpb[rpi * NH_ + h];
#pragma unroll
        for (int cls = 0; cls < 8; cls++) {
            float mask = (((cls & 4) && dd) || ((cls & 2) && dh) || ((cls & 1) && dw))
                             ? -100.0f : 0.0f;
            g_tbl[(((long)cls * NH_ + h) * NN_ + n) * NN_ + m] = __float2half(bias + mask);
        }
    }
}

// ---------------- K3: attention — 128 thr/CTA, K and V staged in smem ------------
#define VPAD 136
__global__ void __launch_bounds__(128, 5) attn_kernel() {
    __shared__ half sVt[16 * VPAD];
    __shared__ half sK[128 * 16];

    int bw = blockIdx.x >> 4;
    int h  = (blockIdx.x >> 1) & 7;
    int rh = blockIdx.x & 1;
    int tid = threadIdx.x, wid = tid >> 5, lane = tid & 31;
    int g = lane >> 2, t = lane & 3;
    long tokbase = (long)bw * 128;
    const half* Qp = g_qkvh + ((long)h * NTOK + tokbase) * 16;
    const half* Kp = g_qkvh + ((long)(8 + h) * NTOK + tokbase) * 16;
    const half* Vp = g_qkvh + ((long)(16 + h) * NTOK + tokbase) * 16;

    // stage K (linear) and V^T (dim-major) into smem — coalesced
    {
        int tok = tid;
        uint4 kv0 = *(const uint4*)(Kp + tok * 16);
        uint4 kv1 = *(const uint4*)(Kp + tok * 16 + 8);
        *(uint4*)&sK[tok * 16]     = kv0;
        *(uint4*)&sK[tok * 16 + 8] = kv1;
        uint4 hv0 = *(const uint4*)(Vp + tok * 16);
        uint4 hv1 = *(const uint4*)(Vp + tok * 16 + 8);
        const half* h0 = (const half*)&hv0;
        const half* h1 = (const half*)&hv1;
#pragma unroll
        for (int d = 0; d < 8; d++) {
            sVt[d * VPAD + tok]       = h0[d];
            sVt[(8 + d) * VPAD + tok] = h1[d];
        }
    }
    __syncthreads();

    // Q fragments (q pre-scaled by 0.25 in the QKV epilogue)
    int row0 = rh * 64 + wid * 16;
    uint32_t qf[4];
    qf[0] = *(const uint32_t*)(Qp + (row0 + g) * 16 + 2 * t);
    qf[1] = *(const uint32_t*)(Qp + (row0 + g + 8) * 16 + 2 * t);
    qf[2] = *(const uint32_t*)(Qp + (row0 + g) * 16 + 2 * t + 8);
    qf[3] = *(const uint32_t*)(Qp + (row0 + g + 8) * 16 + 2 * t + 8);

    // QK^T from smem K
    float acc[16][4];
#pragma unroll
    for (int j = 0; j < 16; j++) {
        uint32_t kf[2];
        kf[0] = *(const uint32_t*)&sK[(8 * j + g) * 16 + 2 * t];
        kf[1] = *(const uint32_t*)&sK[(8 * j + g) * 16 + 2 * t + 8];
        acc[j][0] = acc[j][1] = acc[j][2] = acc[j][3] = 0.0f;
        MMA(acc[j], qf, kf);
    }

    // bias+mask table (fp16) + exp + row sums — no branches
    int wi = bw & 255;
    int cls = (((wi >> 6) == 3) ? 4 : 0) | ((((wi >> 3) & 7) == 7) ? 2 : 0) |
              (((wi & 7) == 7) ? 1 : 0);
    const half* bptr = g_tbl + ((long)cls * NH_ + h) * NN_ * NN_;
    float sum_g = 0.0f, sum_g8 = 0.0f;
#pragma unroll
    for (int j = 0; j < 16; j++) {
        int col = 8 * j + 2 * t;
        float2 bg  = __half22float2(*(const half2*)(bptr + (row0 + g) * NN_ + col));
        float2 bg8 = __half22float2(*(const half2*)(bptr + (row0 + g + 8) * NN_ + col));
        float e0 = __expf(acc[j][0] + bg.x);
        float e1 = __expf(acc[j][1] + bg.y);
        float e2 = __expf(acc[j][2] + bg8.x);
        float e3 = __expf(acc[j][3] + bg8.y);
        acc[j][0] = e0; acc[j][1] = e1; acc[j][2] = e2; acc[j][3] = e3;
        sum_g += e0 + e1; sum_g8 += e2 + e3;
    }
    sum_g  += __shfl_xor_sync(0xffffffffu, sum_g, 1);
    sum_g  += __shfl_xor_sync(0xffffffffu, sum_g, 2);
    sum_g8 += __shfl_xor_sync(0xffffffffu, sum_g8, 1);
    sum_g8 += __shfl_xor_sync(0xffffffffu, sum_g8, 2);
    float rs_g = 1.0f / sum_g, rs_g8 = 1.0f / sum_g8;

    // P @ V
    float oacc[2][4];
#pragma unroll
    for (int nj = 0; nj < 2; nj++)
#pragma unroll
        for (int c = 0; c < 4; c++) oacc[nj][c] = 0.0f;

#pragma unroll
    for (int kt = 0; kt < 8; kt++) {
        float* p0 = acc[2 * kt];
        float* p1 = acc[2 * kt + 1];
        uint32_t pf[4];
        pf[0] = packh2(p0[0], p0[1]);
        pf[1] = packh2(p0[2], p0[3]);
        pf[2] = packh2(p1[0], p1[1]);
        pf[3] = packh2(p1[2], p1[3]);
#pragma unroll
        for (int nj = 0; nj < 2; nj++) {
            int vb = (8 * nj + g) * VPAD + 16 * kt + 2 * t;
            uint32_t vf[2];
            vf[0] = *(const uint32_t*)&sVt[vb];
            vf[1] = *(const uint32_t*)&sVt[vb + 8];
            MMA(oacc[nj], pf, vf);
        }
    }

    long og  = (tokbase + row0 + g) * 128 + h * 16;
    long og8 = og + 8 * 128;
#pragma unroll
    for (int nj = 0; nj < 2; nj++) {
        int dn = 8 * nj + 2 * t;
        *(half2*)(g_attn + og + dn)  = __floats2half2_rn(oacc[nj][0] * rs_g,
                                                         oacc[nj][1] * rs_g);
        *(half2*)(g_attn + og8 + dn) = __floats2half2_rn(oacc[nj][2] * rs_g8,
                                                         oacc[nj][3] * rs_g8);
    }
}

// -------- K6: window-reverse + roll + residual + LN2 (-> x1 f32, xn2 fp16) -------
__global__ void scatter_ln2_kernel(const float* __restrict__ x,
                                   const float* __restrict__ g2,
                                   const float* __restrict__ b2) {
    int tk = (blockIdx.x * blockDim.x + threadIdx.x) >> 5;
    int lane = threadIdx.x & 31;
    if (tk >= NTOK) return;
    int w = tk & 63, h = (tk >> 6) & 63, d = (tk >> 12) & 7, bb = tk >> 15;
    int sd = (d + 7) & 7;
    int sh = (h + 60) & 63;
    int sw = (w + 60) & 63;
    int bw = bb * 256 + (sd >> 1) * 64 + (sh >> 3) * 8 + (sw >> 3);
    int n  = (sd & 1) * 64 + (sh & 7) * 8 + (sw & 7);

    float4 xv = *(const float4*)(x + (long)tk * C_ + lane * 4);
    uint2 pvh = *(const uint2*)(g_projout_h + ((long)bw * NN_ + n) * C_ + lane * 4);
    float2 p01 = __half22float2(*(half2*)&pvh.x);
    float2 p23 = __half22float2(*(half2*)&pvh.y);
    float4 s1;
    s1.x = xv.x + p01.x; s1.y = xv.y + p01.y;
    s1.z = xv.z + p23.x; s1.w = xv.w + p23.y;
    *(float4*)(g_x1 + (long)tk * C_ + lane * 4) = s1;

    float s  = s1.x + s1.y + s1.z + s1.w;
    float sq = s1.x * s1.x + s1.y * s1.y + s1.z * s1.z + s1.w * s1.w;
#pragma unroll
    for (int o = 16; o > 0; o >>= 1) {
        s  += __shfl_xor_sync(0xffffffffu, s, o);
        sq += __shfl_xor_sync(0xffffffffu, sq, o);
    }
    float mean = s * (1.0f / C_);
    float var  = sq * (1.0f / C_) - mean * mean;
    float inv  = rsqrtf(var + 1e-5f);
    float4 gg = *(const float4*)(g2 + lane * 4);
    float4 bv = *(const float4*)(b2 + lane * 4);
    long o = (long)tk * C_ + lane * 4;
    *(half2*)(g_xn2 + o)     = __floats2half2_rn((s1.x - mean) * inv * gg.x + bv.x,
                                                 (s1.y - mean) * inv * gg.y + bv.y);
    *(half2*)(g_xn2 + o + 2) = __floats2half2_rn((s1.z - mean) * inv * gg.z + bv.z,
                                                 (s1.w - mean) * inv * gg.w + bv.w);
}

// ---------------------------------------------------------------------------
extern "C" void kernel_launch(void* const* d_in, const int* in_sizes, int n_in,
                              void* d_out, int out_size) {
    const float* x      = (const float*)d_in[0];
    const float* qkv_w  = (const float*)d_in[1];
    const float* qkv_b  = (const float*)d_in[2];
    const float* proj_w = (const float*)d_in[3];
    const float* proj_b = (const float*)d_in[4];
    const float* rpb    = (const float*)d_in[5];
    const float* ln1_g  = (const float*)d_in[6];
    const float* ln1_b  = (const float*)d_in[7];
    const float* ln2_g  = (const float*)d_in[8];
    const float* ln2_b  = (const float*)d_in[9];
    const float* fc1_w  = (const float*)d_in[10];
    const float* fc1_b  = (const float*)d_in[11];
    const float* fc2_w  = (const float*)d_in[12];
    const float* fc2_b  = (const float*)d_in[13];
    float* out = (float*)d_out;

    half *p_win, *p_qkvh, *p_attn, *p_projout_h, *p_xn2, *p_hid;
    half *p_qkvw, *p_projw, *p_fc1w, *p_fc2w;
    float *p_x1;
    cudaGetSymbolAddress((void**)&p_win,       g_win);
    cudaGetSymbolAddress((void**)&p_qkvh,      g_qkvh);
    cudaGetSymbolAddress((void**)&p_attn,      g_attn);
    cudaGetSymbolAddress((void**)&p_projout_h, g_projout_h);
    cudaGetSymbolAddress((void**)&p_xn2,       g_xn2);
    cudaGetSymbolAddress((void**)&p_hid,       g_hid);
    cudaGetSymbolAddress((void**)&p_qkvw,      g_qkvw);
    cudaGetSymbolAddress((void**)&p_projw,     g_projw);
    cudaGetSymbolAddress((void**)&p_fc1w,      g_fc1w);
    cudaGetSymbolAddress((void**)&p_fc2w,      g_fc2w);
    cudaGetSymbolAddress((void**)&p_x1,        g_x1);

    const int SMEM = 2 * (128 + 64) * PADK * 2;   // 55296 B
    cudaFuncSetAttribute(mma_gemm<0, false, 2>, cudaFuncAttributeMaxDynamicSharedMemorySize, SMEM);
    cudaFuncSetAttribute(mma_gemm<0, false, 1>, cudaFuncAttributeMaxDynamicSharedMemorySize, SMEM);
    cudaFuncSetAttribute(mma_gemm<1, false, 1>, cudaFuncAttributeMaxDynamicSharedMemorySize, SMEM);
    cudaFuncSetAttribute(mma_gemm<0, true, 0>,  cudaFuncAttributeMaxDynamicSharedMemorySize, SMEM);

    // 0) weight convert + bias/mask table
    convert_weights<<<256, 256>>>(qkv_w, proj_w, fc1_w, fc2_w);
    bias_kernel<<<128, 128>>>(rpb);

    // 1) LN1 + shift + partition
    ln_gather_kernel<<<8192, 256>>>(x, ln1_g, ln1_b);
    // 2) QKV GEMM -> head-major fp16 (q pre-scaled)
    mma_gemm<0, false, 2><<<dim3(6, 512), 256, SMEM>>>(
        p_win, p_qkvw, qkv_b, nullptr, nullptr, p_qkvh, 384, 128);
    // 3) attention
    attn_kernel<<<NWIN * NH_ * 2, 128>>>();
    // 4) proj GEMM -> fp16
    mma_gemm<0, false, 1><<<dim3(2, 512), 256, SMEM>>>(
        p_attn, p_projw, proj_b, nullptr, nullptr, p_projout_h, 128, 128);
    // 5) reverse + roll + residual + LN2
    scatter_ln2_kernel<<<8192, 256>>>(x, ln2_g, ln2_b);
    // 6) fc1 + GELU -> fp16
    mma_gemm<1, false, 1><<<dim3(8, 512), 256, SMEM>>>(
        p_xn2, p_fc1w, fc1_b, nullptr, nullptr, p_hid, 512, 128);
    // 7) fc2 + residual -> out (f32)
    mma_gemm<0, true, 0><<<dim3(2, 512), 256, SMEM>>>(
        p_hid, p_fc2w, fc2_b, p_x1, out, nullptr, 128, 512);
}

// round 15
// speedup vs baseline: 1.3008x; 1.0445x over previous
#include <cuda_runtime.h>
#include <cuda_fp16.h>
#include <math.h>
#include <stdint.h>

// Problem constants
#define B_    2
#define D_    8
#define C_    128
#define NH_   8
#define NTOK  65536
#define NWIN  512
#define NN_   128
#define MLPH  512

// ---------------- scratch (device globals) -----------------------------------
__device__ half  g_win[NTOK * C_];
__device__ half  g_qkvh[24LL * NTOK * 16];    // [part(3)][head(8)][tok][16]
__device__ half  g_tbl[8LL * NH_ * NN_ * NN_]; // [class][h][n][m] bias+mask fp16
__device__ half  g_attn[NTOK * C_];
__device__ half  g_projout_h[NTOK * C_];
__device__ float g_x1[NTOK * C_];
__device__ half  g_xn2[NTOK * C_];
__device__ half  g_hid[(long)NTOK * MLPH];
// fp16 weights
__device__ half  g_qkvw[384 * C_];
__device__ half  g_projw[C_ * C_];
__device__ half  g_fc1w[MLPH * C_];
__device__ half  g_fc2w[C_ * MLPH];

__device__ __forceinline__ float gelu_exact(float x) {
    return 0.5f * x * (1.0f + erff(x * 0.70710678118654752f));
}

// ---- mma.sync m16n8k16 f16 -> f32 ------------------------------------------------
#define MMA(d, a, b)                                                            \
    asm volatile("mma.sync.aligned.m16n8k16.row.col.f32.f16.f16.f32 "           \
        "{%0,%1,%2,%3}, {%4,%5,%6,%7}, {%8,%9}, {%0,%1,%2,%3};"                 \
        : "+f"((d)[0]), "+f"((d)[1]), "+f"((d)[2]), "+f"((d)[3])                \
        : "r"((a)[0]), "r"((a)[1]), "r"((a)[2]), "r"((a)[3]),                    \
          "r"((b)[0]), "r"((b)[1]))

#define LDMX4(r, addr)                                                          \
    asm volatile("ldmatrix.sync.aligned.m8n8.x4.shared.b16 {%0,%1,%2,%3}, [%4];"\
        : "=r"((r)[0]), "=r"((r)[1]), "=r"((r)[2]), "=r"((r)[3]) : "r"(addr))

__device__ __forceinline__ uint32_t packh2(float v0, float v1) {
    half2 h = __floats2half2_rn(v0, v1);
    return *(uint32_t*)&h;
}
__device__ __forceinline__ uint32_t smem_u32(const void* p) {
    uint32_t a;
    asm("{ .reg .u64 t; cvta.to.shared.u64 t, %1; cvt.u32.u64 %0, t; }" : "=r"(a) : "l"(p));
    return a;
}
__device__ __forceinline__ void cpa16(uint32_t d, const void* s) {
    asm volatile("cp.async.cg.shared.global [%0], [%1], 16;" :: "r"(d), "l"(s));
}
#define CP_COMMIT() asm volatile("cp.async.commit_group;" ::: "memory")
#define CP_WAIT0()  asm volatile("cp.async.wait_group 0;" ::: "memory")
#define CP_WAIT1()  asm volatile("cp.async.wait_group 1;" ::: "memory")

// ==================  GEMM: BM=128 BN=64 BK=64, 256 thr, 3 CTAs/SM  ================
#define PADK 72
#define BUFA (128 * PADK * 2)
#define BUFW (64 * PADK * 2)

template <int ACT, bool RES, int OMODE, bool FULLK>
__global__ void __launch_bounds__(256, 3)
mma_gemm(const half* __restrict__ A, const half* __restrict__ W,
         const float* __restrict__ bias, const float* __restrict__ res,
         float* __restrict__ Cf, half* __restrict__ Chf,
         int N, int K) {
    extern __shared__ half smem[];
    half* sA = smem;
    half* sW = smem + 2 * 128 * PADK;
    uint32_t sAu = smem_u32(sA), sWu = smem_u32(sW);

    int tid = threadIdx.x, wid = tid >> 5, lane = tid & 31;
    int g = lane >> 2, t = lane & 3;
    int m0 = blockIdx.y * 128, n0 = blockIdx.x * 64;
    int wm = (wid >> 1) * 32, wn = (wid & 1) * 32;

    float acc[2][4][4];
#pragma unroll
    for (int i = 0; i < 2; i++)
#pragma unroll
        for (int j = 0; j < 4; j++)
#pragma unroll
            for (int c = 0; c < 4; c++) acc[i][j][c] = 0.0f;

    int crow = tid >> 3, cseg = (tid & 7) * 8;
    auto issue = [&](int kc, int buf) {
#pragma unroll
        for (int i = 0; i < 4; i++) {
            int row = crow + i * 32;
            cpa16(sAu + (uint32_t)buf * BUFA + (row * PADK + cseg) * 2,
                  A + (long)(m0 + row) * K + kc + cseg);
        }
#pragma unroll
        for (int i = 0; i < 2; i++) {
            int row = crow + i * 32;
            cpa16(sWu + (uint32_t)buf * BUFW + (row * PADK + cseg) * 2,
                  W + (long)(n0 + row) * K + kc + cseg);
        }
        CP_COMMIT();
    };

    int lrow = lane & 7, lsel = lane >> 3;
    uint32_t aBase = sAu + ((wm + (lsel & 1) * 8 + lrow) * PADK + (lsel >> 1) * 8) * 2;
    uint32_t bBase = sWu + ((wn + (lsel >> 1) * 8 + lrow) * PADK + (lsel & 1) * 8) * 2;

    auto compute_chunk = [&](uint32_t aofs, uint32_t wofs) {
#pragma unroll
        for (int ks = 0; ks < 4; ks++) {
            uint32_t kb2 = ks * 32;
            uint32_t fa[2][4], fb[4][2];
#pragma unroll
            for (int mi = 0; mi < 2; mi++)
                LDMX4(fa[mi], aBase + aofs + mi * (16 * PADK * 2) + kb2);
            LDMX4(fb[0], bBase + wofs + kb2);
            LDMX4(fb[2], bBase + wofs + 16 * PADK * 2 + kb2);
#pragma unroll
            for (int mi = 0; mi < 2; mi++)
#pragma unroll
                for (int nj = 0; nj < 4; nj++)
                    MMA(acc[mi][nj], fa[mi], fb[nj]);
        }
    };

    if (FULLK) {
        issue(0, 0);
        issue(64, 1);
        CP_WAIT0();
        __syncthreads();
        compute_chunk(0, 0);
        compute_chunk(BUFA, BUFW);
    } else {
        int nch = K >> 6;
        issue(0, 0);
        for (int c = 0; c < nch; c++) {
            if (c + 1 < nch) { issue((c + 1) << 6, (c + 1) & 1); CP_WAIT1(); }
            else             { CP_WAIT0(); }
            __syncthreads();
            compute_chunk((uint32_t)(c & 1) * BUFA, (uint32_t)(c & 1) * BUFW);
            __syncthreads();
        }
    }

#pragma unroll
    for (int mi = 0; mi < 2; mi++) {
#pragma unroll
        for (int cr = 0; cr < 2; cr++) {
            int m = m0 + wm + mi * 16 + g + cr * 8;
#pragma unroll
            for (int nj = 0; nj < 4; nj++) {
                int n = n0 + wn + nj * 8 + 2 * t;
                float2 bb = *(const float2*)(bias + n);
                float v0 = acc[mi][nj][cr * 2 + 0] + bb.x;
                float v1 = acc[mi][nj][cr * 2 + 1] + bb.y;
                if (OMODE == 2 && n < 128) { v0 *= 0.25f; v1 *= 0.25f; }
                if (ACT == 1) { v0 = gelu_exact(v0); v1 = gelu_exact(v1); }
                if (RES) {
                    float2 r = *(const float2*)(res + (long)m * N + n);
                    v0 += r.x; v1 += r.y;
                }
                if (OMODE == 2) {
                    int p = n >> 7, hh = (n >> 4) & 7, d = n & 15;
                    long addr = ((long)(p * 8 + hh) * NTOK + m) * 16 + d;
                    *(half2*)(Chf + addr) = __floats2half2_rn(v0, v1);
                } else if (OMODE == 1) {
                    *(half2*)(Chf + (long)m * N + n) = __floats2half2_rn(v0, v1);
                } else {
                    float2 o; o.x = v0; o.y = v1;
                    *(float2*)(Cf + (long)m * N + n) = o;
                }
            }
        }
    }
}

// ---------------- fused weight convert + bias/mask table -------------------------
__global__ void prep_kernel(const float* __restrict__ qkv_w,
                            const float* __restrict__ proj_w,
                            const float* __restrict__ fc1_w,
                            const float* __restrict__ fc2_w,
                            const float* __restrict__ rpb) {
    int blk = blockIdx.x;
    int tid = threadIdx.x;
    if (blk < 256) {
        int i = blk * 256 + tid;
        if (i < 49152) g_qkvw[i] = __float2half(qkv_w[i]);
        if (i < 16384) g_projw[i] = __float2half(proj_w[i]);
        g_fc1w[i] = __float2half(fc1_w[i]);
        g_fc2w[i] = __float2half(fc2_w[i]);
    } else {
        int n = blk - 256;
        if (tid >= 128) return;
        int m = tid;
        int tdn = n >> 6, thn = (n >> 3) & 7, twn = n & 7;
        int tdm = m >> 6, thm = (m >> 3) & 7, twm = m & 7;
        int rpi = (tdn - tdm + 1) * 225 + (thn - thm + 7) * 15 + (twn - twm + 7);
        bool dd = tdn != tdm;
        bool dh = (thn < 4) != (thm < 4);
        bool dw = (twn < 4) != (twm < 4);
#pragma unroll
        for (int h = 0; h < NH_; h++) {
            float bias = rpb[rpi * NH_ + h];
#pragma unroll
            for (int cls = 0; cls < 8; cls++) {
                float mask = (((cls & 4) && dd) || ((cls & 2) && dh) || ((cls & 1) && dw))
                                 ? -100.0f : 0.0f;
                g_tbl[(((long)cls * NH_ + h) * NN_ + n) * NN_ + m] =
                    __float2half(bias + mask);
            }
        }
    }
}

// ---------------- K1: LN1 + cyclic shift + window partition (-> fp16) ------------
__global__ void ln_gather_kernel(const float* __restrict__ x,
                                 const float* __restrict__ g,
                                 const float* __restrict__ b) {
    int warp = (blockIdx.x * blockDim.x + threadIdx.x) >> 5;
    int lane = threadIdx.x & 31;
    if (warp >= NWIN * NN_) return;
    int bw = warp >> 7;
    int n  = warp & 127;
    int bb = bw >> 8;
    int wi = bw & 255;
    int wd = wi >> 6, wh = (wi >> 3) & 7, ww = wi & 7;
    int td = n >> 6,  th = (n >> 3) & 7, tw = n & 7;
    int gd = (wd * 2 + td + 1) & 7;
    int gh = (wh * 8 + th + 4) & 63;
    int gw = (ww * 8 + tw + 4) & 63;
    long src = (((long)(bb * D_ + gd) * 64 + gh) * 64 + gw) * C_;

    float4 v = *(const float4*)(x + src + lane * 4);
    float s  = v.x + v.y + v.z + v.w;
    float sq = v.x * v.x + v.y * v.y + v.z * v.z + v.w * v.w;
#pragma unroll
    for (int o = 16; o > 0; o >>= 1) {
        s  += __shfl_xor_sync(0xffffffffu, s, o);
        sq += __shfl_xor_sync(0xffffffffu, sq, o);
    }
    float mean = s * (1.0f / C_);
    float var  = sq * (1.0f / C_) - mean * mean;
    float inv  = rsqrtf(var + 1e-5f);
    float4 gg = *(const float4*)(g + lane * 4);
    float4 bv = *(const float4*)(b + lane * 4);
    long o = (long)warp * C_ + lane * 4;
    *(half2*)(g_win + o)     = __floats2half2_rn((v.x - mean) * inv * gg.x + bv.x,
                                                 (v.y - mean) * inv * gg.y + bv.y);
    *(half2*)(g_win + o + 2) = __floats2half2_rn((v.z - mean) * inv * gg.z + bv.z,
                                                 (v.w - mean) * inv * gg.w + bv.w);
}

// ---------------- K3: attention — 128 thr/CTA, K and V staged in smem ------------
#define VPAD 136
__global__ void __launch_bounds__(128, 5) attn_kernel() {
    __shared__ half sVt[16 * VPAD];
    __shared__ half sK[128 * 16];

    int bw = blockIdx.x >> 4;
    int h  = (blockIdx.x >> 1) & 7;
    int rh = blockIdx.x & 1;
    int tid = threadIdx.x, wid = tid >> 5, lane = tid & 31;
    int g = lane >> 2, t = lane & 3;
    long tokbase = (long)bw * 128;
    const half* Qp = g_qkvh + ((long)h * NTOK + tokbase) * 16;
    const half* Kp = g_qkvh + ((long)(8 + h) * NTOK + tokbase) * 16;
    const half* Vp = g_qkvh + ((long)(16 + h) * NTOK + tokbase) * 16;

    {
        int tok = tid;
        uint4 kv0 = *(const uint4*)(Kp + tok * 16);
        uint4 kv1 = *(const uint4*)(Kp + tok * 16 + 8);
        *(uint4*)&sK[tok * 16]     = kv0;
        *(uint4*)&sK[tok * 16 + 8] = kv1;
        uint4 hv0 = *(const uint4*)(Vp + tok * 16);
        uint4 hv1 = *(const uint4*)(Vp + tok * 16 + 8);
        const half* h0 = (const half*)&hv0;
        const half* h1 = (const half*)&hv1;
#pragma unroll
        for (int d = 0; d < 8; d++) {
            sVt[d * VPAD + tok]       = h0[d];
            sVt[(8 + d) * VPAD + tok] = h1[d];
        }
    }
    __syncthreads();

    int row0 = rh * 64 + wid * 16;
    uint32_t qf[4];
    qf[0] = *(const uint32_t*)(Qp + (row0 + g) * 16 + 2 * t);
    qf[1] = *(const uint32_t*)(Qp + (row0 + g + 8) * 16 + 2 * t);
    qf[2] = *(const uint32_t*)(Qp + (row0 + g) * 16 + 2 * t + 8);
    qf[3] = *(const uint32_t*)(Qp + (row0 + g + 8) * 16 + 2 * t + 8);

    float acc[16][4];
#pragma unroll
    for (int j = 0; j < 16; j++) {
        uint32_t kf[2];
        kf[0] = *(const uint32_t*)&sK[(8 * j + g) * 16 + 2 * t];
        kf[1] = *(const uint32_t*)&sK[(8 * j + g) * 16 + 2 * t + 8];
        acc[j][0] = acc[j][1] = acc[j][2] = acc[j][3] = 0.0f;
        MMA(acc[j], qf, kf);
    }

    int wi = bw & 255;
    int cls = (((wi >> 6) == 3) ? 4 : 0) | ((((wi >> 3) & 7) == 7) ? 2 : 0) |
              (((wi & 7) == 7) ? 1 : 0);
    const half* bptr = g_tbl + ((long)cls * NH_ + h) * NN_ * NN_;
    float sum_g = 0.0f, sum_g8 = 0.0f;
#pragma unroll
    for (int j = 0; j < 16; j++) {
        int col = 8 * j + 2 * t;
        float2 bg  = __half22float2(*(const half2*)(bptr + (row0 + g) * NN_ + col));
        float2 bg8 = __half22float2(*(const half2*)(bptr + (row0 + g + 8) * NN_ + col));
        float e0 = __expf(acc[j][0] + bg.x);
        float e1 = __expf(acc[j][1] + bg.y);
        float e2 = __expf(acc[j][2] + bg8.x);
        float e3 = __expf(acc[j][3] + bg8.y);
        acc[j][0] = e0; acc[j][1] = e1; acc[j][2] = e2; acc[j][3] = e3;
        sum_g += e0 + e1; sum_g8 += e2 + e3;
    }
    sum_g  += __shfl_xor_sync(0xffffffffu, sum_g, 1);
    sum_g  += __shfl_xor_sync(0xffffffffu, sum_g, 2);
    sum_g8 += __shfl_xor_sync(0xffffffffu, sum_g8, 1);
    sum_g8 += __shfl_xor_sync(0xffffffffu, sum_g8, 2);
    float rs_g = 1.0f / sum_g, rs_g8 = 1.0f / sum_g8;

    float oacc[2][4];
#pragma unroll
    for (int nj = 0; nj < 2; nj++)
#pragma unroll
        for (int c = 0; c < 4; c++) oacc[nj][c] = 0.0f;

#pragma unroll
    for (int kt = 0; kt < 8; kt++) {
        float* p0 = acc[2 * kt];
        float* p1 = acc[2 * kt + 1];
        uint32_t pf[4];
        pf[0] = packh2(p0[0], p0[1]);
        pf[1] = packh2(p0[2], p0[3]);
        pf[2] = packh2(p1[0], p1[1]);
        pf[3] = packh2(p1[2], p1[3]);
#pragma unroll
        for (int nj = 0; nj < 2; nj++) {
            int vb = (8 * nj + g) * VPAD + 16 * kt + 2 * t;
            uint32_t vf[2];
            vf[0] = *(const uint32_t*)&sVt[vb];
            vf[1] = *(const uint32_t*)&sVt[vb + 8];
            MMA(oacc[nj], pf, vf);
        }
    }

    long og  = (tokbase + row0 + g) * 128 + h * 16;
    long og8 = og + 8 * 128;
#pragma unroll
    for (int nj = 0; nj < 2; nj++) {
        int dn = 8 * nj + 2 * t;
        *(half2*)(g_attn + og + dn)  = __floats2half2_rn(oacc[nj][0] * rs_g,
                                                         oacc[nj][1] * rs_g);
        *(half2*)(g_attn + og8 + dn) = __floats2half2_rn(oacc[nj][2] * rs_g8,
                                                         oacc[nj][3] * rs_g8);
    }
}

// -------- K6: window-reverse + roll + residual + LN2 (-> x1 f32, xn2 fp16) -------
__global__ void scatter_ln2_kernel(const float* __restrict__ x,
                                   const float* __restrict__ g2,
                                   const float* __restrict__ b2) {
    int tk = (blockIdx.x * blockDim.x + threadIdx.x) >> 5;
    int lane = threadIdx.x & 31;
    if (tk >= NTOK) return;
    int w = tk & 63, h = (tk >> 6) & 63, d = (tk >> 12) & 7, bb = tk >> 15;
    int sd = (d + 7) & 7;
    int sh = (h + 60) & 63;
    int sw = (w + 60) & 63;
    int bw = bb * 256 + (sd >> 1) * 64 + (sh >> 3) * 8 + (sw >> 3);
    int n  = (sd & 1) * 64 + (sh & 7) * 8 + (sw & 7);

    float4 xv = *(const float4*)(x + (long)tk * C_ + lane * 4);
    uint2 pvh = *(const uint2*)(g_projout_h + ((long)bw * NN_ + n) * C_ + lane * 4);
    float2 p01 = __half22float2(*(half2*)&pvh.x);
    float2 p23 = __half22float2(*(half2*)&pvh.y);
    float4 s1;
    s1.x = xv.x + p01.x; s1.y = xv.y + p01.y;
    s1.z = xv.z + p23.x; s1.w = xv.w + p23.y;
    *(float4*)(g_x1 + (long)tk * C_ + lane * 4) = s1;

    float s  = s1.x + s1.y + s1.z + s1.w;
    float sq = s1.x * s1.x + s1.y * s1.y + s1.z * s1.z + s1.w * s1.w;
#pragma unroll
    for (int o = 16; o > 0; o >>= 1) {
        s  += __shfl_xor_sync(0xffffffffu, s, o);
        sq += __shfl_xor_sync(0xffffffffu, sq, o);
    }
    float mean = s * (1.0f / C_);
    float var  = sq * (1.0f / C_) - mean * mean;
    float inv  = rsqrtf(var + 1e-5f);
    float4 gg = *(const float4*)(g2 + lane * 4);
    float4 bv = *(const float4*)(b2 + lane * 4);
    long o = (long)tk * C_ + lane * 4;
    *(half2*)(g_xn2 + o)     = __floats2half2_rn((s1.x - mean) * inv * gg.x + bv.x,
                                                 (s1.y - mean) * inv * gg.y + bv.y);
    *(half2*)(g_xn2 + o + 2) = __floats2half2_rn((s1.z - mean) * inv * gg.z + bv.z,
                                                 (s1.w - mean) * inv * gg.w + bv.w);
}

// ---------------------------------------------------------------------------
extern "C" void kernel_launch(void* const* d_in, const int* in_sizes, int n_in,
                              void* d_out, int out_size) {
    const float* x      = (const float*)d_in[0];
    const float* qkv_w  = (const float*)d_in[1];
    const float* qkv_b  = (const float*)d_in[2];
    const float* proj_w = (const float*)d_in[3];
    const float* proj_b = (const float*)d_in[4];
    const float* rpb    = (const float*)d_in[5];
    const float* ln1_g  = (const float*)d_in[6];
    const float* ln1_b  = (const float*)d_in[7];
    const float* ln2_g  = (const float*)d_in[8];
    const float* ln2_b  = (const float*)d_in[9];
    const float* fc1_w  = (const float*)d_in[10];
    const float* fc1_b  = (const float*)d_in[11];
    const float* fc2_w  = (const float*)d_in[12];
    const float* fc2_b  = (const float*)d_in[13];
    float* out = (float*)d_out;

    half *p_win, *p_qkvh, *p_attn, *p_projout_h, *p_xn2, *p_hid;
    half *p_qkvw, *p_projw, *p_fc1w, *p_fc2w;
    float *p_x1;
    cudaGetSymbolAddress((void**)&p_win,       g_win);
    cudaGetSymbolAddress((void**)&p_qkvh,      g_qkvh);
    cudaGetSymbolAddress((void**)&p_attn,      g_attn);
    cudaGetSymbolAddress((void**)&p_projout_h, g_projout_h);
    cudaGetSymbolAddress((void**)&p_xn2,       g_xn2);
    cudaGetSymbolAddress((void**)&p_hid,       g_hid);
    cudaGetSymbolAddress((void**)&p_qkvw,      g_qkvw);
    cudaGetSymbolAddress((void**)&p_projw,     g_projw);
    cudaGetSymbolAddress((void**)&p_fc1w,      g_fc1w);
    cudaGetSymbolAddress((void**)&p_fc2w,      g_fc2w);
    cudaGetSymbolAddress((void**)&p_x1,        g_x1);

    const int SMEM = 2 * (128 + 64) * PADK * 2;   // 55296 B
    cudaFuncSetAttribute(mma_gemm<0, false, 2, true>,  cudaFuncAttributeMaxDynamicSharedMemorySize, SMEM);
    cudaFuncSetAttribute(mma_gemm<0, false, 1, true>,  cudaFuncAttributeMaxDynamicSharedMemorySize, SMEM);
    cudaFuncSetAttribute(mma_gemm<1, false, 1, true>,  cudaFuncAttributeMaxDynamicSharedMemorySize, SMEM);
    cudaFuncSetAttribute(mma_gemm<0, true, 0, false>,  cudaFuncAttributeMaxDynamicSharedMemorySize, SMEM);

    // 0) fused weight convert + bias/mask table
    prep_kernel<<<384, 256>>>(qkv_w, proj_w, fc1_w, fc2_w, rpb);
    // 1) LN1 + shift + partition
    ln_gather_kernel<<<8192, 256>>>(x, ln1_g, ln1_b);
    // 2) QKV GEMM -> head-major fp16 (q pre-scaled)
    mma_gemm<0, false, 2, true><<<dim3(6, 512), 256, SMEM>>>(
        p_win, p_qkvw, qkv_b, nullptr, nullptr, p_qkvh, 384, 128);
    // 3) attention
    attn_kernel<<<NWIN * NH_ * 2, 128>>>();
    // 4) proj GEMM -> fp16
    mma_gemm<0, false, 1, true><<<dim3(2, 512), 256, SMEM>>>(
        p_attn, p_projw, proj_b, nullptr, nullptr, p_projout_h, 128, 128);
    // 5) reverse + roll + residual + LN2
    scatter_ln2_kernel<<<8192, 256>>>(x, ln2_g, ln2_b);
    // 6) fc1 + GELU -> fp16
    mma_gemm<1, false, 1, true><<<dim3(8, 512), 256, SMEM>>>(
        p_xn2, p_fc1w, fc1_b, nullptr, nullptr, p_hid, 512, 128);
    // 7) fc2 + residual -> out (f32)
    mma_gemm<0, true, 0, false><<<dim3(2, 512), 256, SMEM>>>(
        p_hid, p_fc2w, fc2_b, p_x1, out, nullptr, 128, 512);
}

// round 16
// speedup vs baseline: 1.4421x; 1.1086x over previous
#include <cuda_runtime.h>
#include <cuda_fp16.h>
#include <math.h>
#include <stdint.h>

// Problem constants
#define B_    2
#define D_    8
#define C_    128
#define NH_   8
#define NTOK  65536
#define NWIN  512
#define NN_   128
#define MLPH  512

// ---------------- scratch (device globals) -----------------------------------
__device__ half  g_win[NTOK * C_];
__device__ half  g_qkvh[24LL * NTOK * 16];     // [part(3)][head(8)][tok][16]
__device__ uint4 g_tblF[131072];               // [cls][h][rb][j2][lane] fragment-order
__device__ half  g_attn[NTOK * C_];
__device__ half  g_projout_h[NTOK * C_];
__device__ float g_x1[NTOK * C_];
__device__ half  g_xn2[NTOK * C_];
__device__ half  g_hid[(long)NTOK * MLPH];
// fp16 weights
__device__ half  g_qkvw[384 * C_];
__device__ half  g_projw[C_ * C_];
__device__ half  g_fc1w[MLPH * C_];
__device__ half  g_fc2w[C_ * MLPH];

__device__ __forceinline__ float gelu_exact(float x) {
    return 0.5f * x * (1.0f + erff(x * 0.70710678118654752f));
}

// ---- mma.sync m16n8k16 f16 -> f32 ------------------------------------------------
#define MMA(d, a, b)                                                            \
    asm volatile("mma.sync.aligned.m16n8k16.row.col.f32.f16.f16.f32 "           \
        "{%0,%1,%2,%3}, {%4,%5,%6,%7}, {%8,%9}, {%0,%1,%2,%3};"                 \
        : "+f"((d)[0]), "+f"((d)[1]), "+f"((d)[2]), "+f"((d)[3])                \
        : "r"((a)[0]), "r"((a)[1]), "r"((a)[2]), "r"((a)[3]),                    \
          "r"((b)[0]), "r"((b)[1]))

#define LDMX4(r, addr)                                                          \
    asm volatile("ldmatrix.sync.aligned.m8n8.x4.shared.b16 {%0,%1,%2,%3}, [%4];"\
        : "=r"((r)[0]), "=r"((r)[1]), "=r"((r)[2]), "=r"((r)[3]) : "r"(addr))

__device__ __forceinline__ uint32_t packh2(float v0, float v1) {
    half2 h = __floats2half2_rn(v0, v1);
    return *(uint32_t*)&h;
}
__device__ __forceinline__ uint32_t smem_u32(const void* p) {
    uint32_t a;
    asm("{ .reg .u64 t; cvta.to.shared.u64 t, %1; cvt.u32.u64 %0, t; }" : "=r"(a) : "l"(p));
    return a;
}
__device__ __forceinline__ void cpa16(uint32_t d, const void* s) {
    asm volatile("cp.async.cg.shared.global [%0], [%1], 16;" :: "r"(d), "l"(s));
}
#define CP_COMMIT() asm volatile("cp.async.commit_group;" ::: "memory")
#define CP_WAIT0()  asm volatile("cp.async.wait_group 0;" ::: "memory")
#define CP_WAIT1()  asm volatile("cp.async.wait_group 1;" ::: "memory")

// ==================  GEMM: BM=128 BN=64 BK=64, 256 thr, 3 CTAs/SM  ================
#define PADK 72
#define BUFA (128 * PADK * 2)
#define BUFW (64 * PADK * 2)

template <int ACT, bool RES, int OMODE, bool FULLK>
__global__ void __launch_bounds__(256, 3)
mma_gemm(const half* __restrict__ A, const half* __restrict__ W,
         const float* __restrict__ bias, const float* __restrict__ res,
         float* __restrict__ Cf, half* __restrict__ Chf,
         int N, int K) {
    extern __shared__ half smem[];
    half* sA = smem;
    half* sW = smem + 2 * 128 * PADK;
    uint32_t sAu = smem_u32(sA), sWu = smem_u32(sW);

    int tid = threadIdx.x, wid = tid >> 5, lane = tid & 31;
    int g = lane >> 2, t = lane & 3;
    int m0 = blockIdx.y * 128, n0 = blockIdx.x * 64;
    int wm = (wid >> 1) * 32, wn = (wid & 1) * 32;

    float acc[2][4][4];
#pragma unroll
    for (int i = 0; i < 2; i++)
#pragma unroll
        for (int j = 0; j < 4; j++)
#pragma unroll
            for (int c = 0; c < 4; c++) acc[i][j][c] = 0.0f;

    int crow = tid >> 3, cseg = (tid & 7) * 8;
    auto issue = [&](int kc, int buf) {
#pragma unroll
        for (int i = 0; i < 4; i++) {
            int row = crow + i * 32;
            cpa16(sAu + (uint32_t)buf * BUFA + (row * PADK + cseg) * 2,
                  A + (long)(m0 + row) * K + kc + cseg);
        }
#pragma unroll
        for (int i = 0; i < 2; i++) {
            int row = crow + i * 32;
            cpa16(sWu + (uint32_t)buf * BUFW + (row * PADK + cseg) * 2,
                  W + (long)(n0 + row) * K + kc + cseg);
        }
        CP_COMMIT();
    };

    int lrow = lane & 7, lsel = lane >> 3;
    uint32_t aBase = sAu + ((wm + (lsel & 1) * 8 + lrow) * PADK + (lsel >> 1) * 8) * 2;
    uint32_t bBase = sWu + ((wn + (lsel >> 1) * 8 + lrow) * PADK + (lsel & 1) * 8) * 2;

    auto compute_chunk = [&](uint32_t aofs, uint32_t wofs) {
#pragma unroll
        for (int ks = 0; ks < 4; ks++) {
            uint32_t kb2 = ks * 32;
            uint32_t fa[2][4], fb[4][2];
#pragma unroll
            for (int mi = 0; mi < 2; mi++)
                LDMX4(fa[mi], aBase + aofs + mi * (16 * PADK * 2) + kb2);
            LDMX4(fb[0], bBase + wofs + kb2);
            LDMX4(fb[2], bBase + wofs + 16 * PADK * 2 + kb2);
#pragma unroll
            for (int mi = 0; mi < 2; mi++)
#pragma unroll
                for (int nj = 0; nj < 4; nj++)
                    MMA(acc[mi][nj], fa[mi], fb[nj]);
        }
    };

    if (FULLK) {
        issue(0, 0);
        issue(64, 1);
        CP_WAIT0();
        __syncthreads();
        compute_chunk(0, 0);
        compute_chunk(BUFA, BUFW);
    } else {
        int nch = K >> 6;
        issue(0, 0);
        for (int c = 0; c < nch; c++) {
            if (c + 1 < nch) { issue((c + 1) << 6, (c + 1) & 1); CP_WAIT1(); }
            else             { CP_WAIT0(); }
            __syncthreads();
            compute_chunk((uint32_t)(c & 1) * BUFA, (uint32_t)(c & 1) * BUFW);
            __syncthreads();
        }
    }

#pragma unroll
    for (int mi = 0; mi < 2; mi++) {
#pragma unroll
        for (int cr = 0; cr < 2; cr++) {
            int m = m0 + wm + mi * 16 + g + cr * 8;
#pragma unroll
            for (int nj = 0; nj < 4; nj++) {
                int n = n0 + wn + nj * 8 + 2 * t;
                float2 bb = *(const float2*)(bias + n);
                float v0 = acc[mi][nj][cr * 2 + 0] + bb.x;
                float v1 = acc[mi][nj][cr * 2 + 1] + bb.y;
                if (OMODE == 2 && n < 128) { v0 *= 0.25f; v1 *= 0.25f; }
                if (ACT == 1) { v0 = gelu_exact(v0); v1 = gelu_exact(v1); }
                if (RES) {
                    float2 r = *(const float2*)(res + (long)m * N + n);
                    v0 += r.x; v1 += r.y;
                }
                if (OMODE == 2) {
                    int p = n >> 7, hh = (n >> 4) & 7, d = n & 15;
                    long addr = ((long)(p * 8 + hh) * NTOK + m) * 16 + d;
                    *(half2*)(Chf + addr) = __floats2half2_rn(v0, v1);
                } else if (OMODE == 1) {
                    *(half2*)(Chf + (long)m * N + n) = __floats2half2_rn(v0, v1);
                } else {
                    float2 o; o.x = v0; o.y = v1;
                    *(float2*)(Cf + (long)m * N + n) = o;
                }
            }
        }
    }
}

// ---------------- fused weight convert + fragment-ordered bias/mask table --------
__device__ __forceinline__ half tbl_entry(const float* rpb, int cls, int h,
                                          int n, int m) {
    int tdn = n >> 6, thn = (n >> 3) & 7, twn = n & 7;
    int tdm = m >> 6, thm = (m >> 3) & 7, twm = m & 7;
    int rpi = (tdn - tdm + 1) * 225 + (thn - thm + 7) * 15 + (twn - twm + 7);
    bool dd = tdn != tdm;
    bool dh = (thn < 4) != (thm < 4);
    bool dw = (twn < 4) != (twm < 4);
    float mask = (((cls & 4) && dd) || ((cls & 2) && dh) || ((cls & 1) && dw))
                     ? -100.0f : 0.0f;
    return __float2half(rpb[rpi * NH_ + h] + mask);
}

__global__ void prep_kernel(const float* __restrict__ qkv_w,
                            const float* __restrict__ proj_w,
                            const float* __restrict__ fc1_w,
                            const float* __restrict__ fc2_w,
                            const float* __restrict__ rpb) {
    int blk = blockIdx.x;
    int tid = threadIdx.x;
    if (blk < 256) {
        int i = blk * 256 + tid;
        if (i < 49152) g_qkvw[i] = __float2half(qkv_w[i]);
        if (i < 16384) g_projw[i] = __float2half(proj_w[i]);
        g_fc1w[i] = __float2half(fc1_w[i]);
        g_fc2w[i] = __float2half(fc2_w[i]);
    } else {
        // fragment-ordered table: idx over [cls(8)][h(8)][rb(8)][j2(8)][lane(32)]
        int idx = (blk - 256) * 256 + tid;   // 0..131071
        int lane = idx & 31;
        int j2   = (idx >> 5) & 7;
        int rb   = (idx >> 8) & 7;
        int h    = (idx >> 11) & 7;
        int cls  = (idx >> 14) & 7;
        int g = lane >> 2, t = lane & 3;
        int row  = rb * 16 + g;
        half v[8];
#pragma unroll
        for (int jj = 0; jj < 2; jj++) {
            int col = 8 * (2 * j2 + jj) + 2 * t;
            v[jj * 4 + 0] = tbl_entry(rpb, cls, h, row,     col);
            v[jj * 4 + 1] = tbl_entry(rpb, cls, h, row,     col + 1);
            v[jj * 4 + 2] = tbl_entry(rpb, cls, h, row + 8, col);
            v[jj * 4 + 3] = tbl_entry(rpb, cls, h, row + 8, col + 1);
        }
        g_tblF[idx] = *(uint4*)v;
    }
}

// ---------------- K1: LN1 + cyclic shift + window partition (-> fp16) ------------
__global__ void ln_gather_kernel(const float* __restrict__ x,
                                 const float* __restrict__ g,
                                 const float* __restrict__ b) {
    int warp = (blockIdx.x * blockDim.x + threadIdx.x) >> 5;
    int lane = threadIdx.x & 31;
    if (warp >= NWIN * NN_) return;
    int bw = warp >> 7;
    int n  = warp & 127;
    int bb = bw >> 8;
    int wi = bw & 255;
    int wd = wi >> 6, wh = (wi >> 3) & 7, ww = wi & 7;
    int td = n >> 6,  th = (n >> 3) & 7, tw = n & 7;
    int gd = (wd * 2 + td + 1) & 7;
    int gh = (wh * 8 + th + 4) & 63;
    int gw = (ww * 8 + tw + 4) & 63;
    long src = (((long)(bb * D_ + gd) * 64 + gh) * 64 + gw) * C_;

    float4 v = *(const float4*)(x + src + lane * 4);
    float s  = v.x + v.y + v.z + v.w;
    float sq = v.x * v.x + v.y * v.y + v.z * v.z + v.w * v.w;
#pragma unroll
    for (int o = 16; o > 0; o >>= 1) {
        s  += __shfl_xor_sync(0xffffffffu, s, o);
        sq += __shfl_xor_sync(0xffffffffu, sq, o);
    }
    float mean = s * (1.0f / C_);
    float var  = sq * (1.0f / C_) - mean * mean;
    float inv  = rsqrtf(var + 1e-5f);
    float4 gg = *(const float4*)(g + lane * 4);
    float4 bv = *(const float4*)(b + lane * 4);
    long o = (long)warp * C_ + lane * 4;
    *(half2*)(g_win + o)     = __floats2half2_rn((v.x - mean) * inv * gg.x + bv.x,
                                                 (v.y - mean) * inv * gg.y + bv.y);
    *(half2*)(g_win + o + 2) = __floats2half2_rn((v.z - mean) * inv * gg.z + bv.z,
                                                 (v.w - mean) * inv * gg.w + bv.w);
}

// ---------------- K3: attention — 128 thr/CTA, fragment-ordered bias loads -------
#define VPAD 136
__global__ void __launch_bounds__(128, 5) attn_kernel() {
    __shared__ half sVt[16 * VPAD];
    __shared__ half sK[128 * 16];

    int bw = blockIdx.x >> 4;
    int h  = (blockIdx.x >> 1) & 7;
    int rh = blockIdx.x & 1;
    int tid = threadIdx.x, wid = tid >> 5, lane = tid & 31;
    int g = lane >> 2, t = lane & 3;
    long tokbase = (long)bw * 128;
    const half* Qp = g_qkvh + ((long)h * NTOK + tokbase) * 16;
    const half* Kp = g_qkvh + ((long)(8 + h) * NTOK + tokbase) * 16;
    const half* Vp = g_qkvh + ((long)(16 + h) * NTOK + tokbase) * 16;

    {
        int tok = tid;
        uint4 kv0 = *(const uint4*)(Kp + tok * 16);
        uint4 kv1 = *(const uint4*)(Kp + tok * 16 + 8);
        *(uint4*)&sK[tok * 16]     = kv0;
        *(uint4*)&sK[tok * 16 + 8] = kv1;
        uint4 hv0 = *(const uint4*)(Vp + tok * 16);
        uint4 hv1 = *(const uint4*)(Vp + tok * 16 + 8);
        const half* h0 = (const half*)&hv0;
        const half* h1 = (const half*)&hv1;
#pragma unroll
        for (int d = 0; d < 8; d++) {
            sVt[d * VPAD + tok]       = h0[d];
            sVt[(8 + d) * VPAD + tok] = h1[d];
        }
    }
    __syncthreads();

    int row0 = rh * 64 + wid * 16;
    uint32_t qf[4];
    qf[0] = *(const uint32_t*)(Qp + (row0 + g) * 16 + 2 * t);
    qf[1] = *(const uint32_t*)(Qp + (row0 + g + 8) * 16 + 2 * t);
    qf[2] = *(const uint32_t*)(Qp + (row0 + g) * 16 + 2 * t + 8);
    qf[3] = *(const uint32_t*)(Qp + (row0 + g + 8) * 16 + 2 * t + 8);

    float acc[16][4];
#pragma unroll
    for (int j = 0; j < 16; j++) {
        uint32_t kf[2];
        kf[0] = *(const uint32_t*)&sK[(8 * j + g) * 16 + 2 * t];
        kf[1] = *(const uint32_t*)&sK[(8 * j + g) * 16 + 2 * t + 8];
        acc[j][0] = acc[j][1] = acc[j][2] = acc[j][3] = 0.0f;
        MMA(acc[j], qf, kf);
    }

    // fragment-ordered bias+mask: 8 coalesced uint4 loads
    int wi = bw & 255;
    int cls = (((wi >> 6) == 3) ? 4 : 0) | ((((wi >> 3) & 7) == 7) ? 2 : 0) |
              (((wi & 7) == 7) ? 1 : 0);
    int rb = rh * 4 + wid;
    const uint4* bF = g_tblF + ((((long)cls * 8 + h) * 8 + rb) * 8) * 32 + lane;
    float sum_g = 0.0f, sum_g8 = 0.0f;
#pragma unroll
    for (int j2 = 0; j2 < 8; j2++) {
        uint4 bv = bF[j2 * 32];
        const half2* hp = (const half2*)&bv;
        int j = 2 * j2;
#pragma unroll
        for (int jj = 0; jj < 2; jj++) {
            float2 brow  = __half22float2(hp[jj * 2 + 0]);  // (row, col),(row, col+1)
            float2 brow8 = __half22float2(hp[jj * 2 + 1]);  // (row+8, ...)
            float e0 = __expf(acc[j + jj][0] + brow.x);
            float e1 = __expf(acc[j + jj][1] + brow.y);
            float e2 = __expf(acc[j + jj][2] + brow8.x);
            float e3 = __expf(acc[j + jj][3] + brow8.y);
            acc[j + jj][0] = e0; acc[j + jj][1] = e1;
            acc[j + jj][2] = e2; acc[j + jj][3] = e3;
            sum_g += e0 + e1; sum_g8 += e2 + e3;
        }
    }
    sum_g  += __shfl_xor_sync(0xffffffffu, sum_g, 1);
    sum_g  += __shfl_xor_sync(0xffffffffu, sum_g, 2);
    sum_g8 += __shfl_xor_sync(0xffffffffu, sum_g8, 1);
    sum_g8 += __shfl_xor_sync(0xffffffffu, sum_g8, 2);
    float rs_g = 1.0f / sum_g, rs_g8 = 1.0f / sum_g8;

    float oacc[2][4];
#pragma unroll
    for (int nj = 0; nj < 2; nj++)
#pragma unroll
        for (int c = 0; c < 4; c++) oacc[nj][c] = 0.0f;

#pragma unroll
    for (int kt = 0; kt < 8; kt++) {
        float* p0 = acc[2 * kt];
        float* p1 = acc[2 * kt + 1];
        uint32_t pf[4];
        pf[0] = packh2(p0[0], p0[1]);
        pf[1] = packh2(p0[2], p0[3]);
        pf[2] = packh2(p1[0], p1[1]);
        pf[3] = packh2(p1[2], p1[3]);
#pragma unroll
        for (int nj = 0; nj < 2; nj++) {
            int vb = (8 * nj + g) * VPAD + 16 * kt + 2 * t;
            uint32_t vf[2];
            vf[0] = *(const uint32_t*)&sVt[vb];
            vf[1] = *(const uint32_t*)&sVt[vb + 8];
            MMA(oacc[nj], pf, vf);
        }
    }

    long og  = (tokbase + row0 + g) * 128 + h * 16;
    long og8 = og + 8 * 128;
#pragma unroll
    for (int nj = 0; nj < 2; nj++) {
        int dn = 8 * nj + 2 * t;
        *(half2*)(g_attn + og + dn)  = __floats2half2_rn(oacc[nj][0] * rs_g,
                                                         oacc[nj][1] * rs_g);
        *(half2*)(g_attn + og8 + dn) = __floats2half2_rn(oacc[nj][2] * rs_g8,
                                                         oacc[nj][3] * rs_g8);
    }
}

// -------- K6: window-reverse + roll + residual + LN2 (-> x1 f32, xn2 fp16) -------
__global__ void scatter_ln2_kernel(const float* __restrict__ x,
                                   const float* __restrict__ g2,
                                   const float* __restrict__ b2) {
    int tk = (blockIdx.x * blockDim.x + threadIdx.x) >> 5;
    int lane = threadIdx.x & 31;
    if (tk >= NTOK) return;
    int w = tk & 63, h = (tk >> 6) & 63, d = (tk >> 12) & 7, bb = tk >> 15;
    int sd = (d + 7) & 7;
    int sh = (h + 60) & 63;
    int sw = (w + 60) & 63;
    int bw = bb * 256 + (sd >> 1) * 64 + (sh >> 3) * 8 + (sw >> 3);
    int n  = (sd & 1) * 64 + (sh & 7) * 8 + (sw & 7);

    float4 xv = *(const float4*)(x + (long)tk * C_ + lane * 4);
    uint2 pvh = *(const uint2*)(g_projout_h + ((long)bw * NN_ + n) * C_ + lane * 4);
    float2 p01 = __half22float2(*(half2*)&pvh.x);
    float2 p23 = __half22float2(*(half2*)&pvh.y);
    float4 s1;
    s1.x = xv.x + p01.x; s1.y = xv.y + p01.y;
    s1.z = xv.z + p23.x; s1.w = xv.w + p23.y;
    *(float4*)(g_x1 + (long)tk * C_ + lane * 4) = s1;

    float s  = s1.x + s1.y + s1.z + s1.w;
    float sq = s1.x * s1.x + s1.y * s1.y + s1.z * s1.z + s1.w * s1.w;
#pragma unroll
    for (int o = 16; o > 0; o >>= 1) {
        s  += __shfl_xor_sync(0xffffffffu, s, o);
        sq += __shfl_xor_sync(0xffffffffu, sq, o);
    }
    float mean = s * (1.0f / C_);
    float var  = sq * (1.0f / C_) - mean * mean;
    float inv  = rsqrtf(var + 1e-5f);
    float4 gg = *(const float4*)(g2 + lane * 4);
    float4 bv = *(const float4*)(b2 + lane * 4);
    long o = (long)tk * C_ + lane * 4;
    *(half2*)(g_xn2 + o)     = __floats2half2_rn((s1.x - mean) * inv * gg.x + bv.x,
                                                 (s1.y - mean) * inv * gg.y + bv.y);
    *(half2*)(g_xn2 + o + 2) = __floats2half2_rn((s1.z - mean) * inv * gg.z + bv.z,
                                                 (s1.w - mean) * inv * gg.w + bv.w);
}

// ---------------------------------------------------------------------------
extern "C" void kernel_launch(void* const* d_in, const int* in_sizes, int n_in,
                              void* d_out, int out_size) {
    const float* x      = (const float*)d_in[0];
    const float* qkv_w  = (const float*)d_in[1];
    const float* qkv_b  = (const float*)d_in[2];
    const float* proj_w = (const float*)d_in[3];
    const float* proj_b = (const float*)d_in[4];
    const float* rpb    = (const float*)d_in[5];
    const float* ln1_g  = (const float*)d_in[6];
    const float* ln1_b  = (const float*)d_in[7];
    const float* ln2_g  = (const float*)d_in[8];
    const float* ln2_b  = (const float*)d_in[9];
    const float* fc1_w  = (const float*)d_in[10];
    const float* fc1_b  = (const float*)d_in[11];
    const float* fc2_w  = (const float*)d_in[12];
    const float* fc2_b  = (const float*)d_in[13];
    float* out = (float*)d_out;

    half *p_win, *p_qkvh, *p_attn, *p_projout_h, *p_xn2, *p_hid;
    half *p_qkvw, *p_projw, *p_fc1w, *p_fc2w;
    float *p_x1;
    cudaGetSymbolAddress((void**)&p_win,       g_win);
    cudaGetSymbolAddress((void**)&p_qkvh,      g_qkvh);
    cudaGetSymbolAddress((void**)&p_attn,      g_attn);
    cudaGetSymbolAddress((void**)&p_projout_h, g_projout_h);
    cudaGetSymbolAddress((void**)&p_xn2,       g_xn2);
    cudaGetSymbolAddress((void**)&p_hid,       g_hid);
    cudaGetSymbolAddress((void**)&p_qkvw,      g_qkvw);
    cudaGetSymbolAddress((void**)&p_projw,     g_projw);
    cudaGetSymbolAddress((void**)&p_fc1w,      g_fc1w);
    cudaGetSymbolAddress((void**)&p_fc2w,      g_fc2w);
    cudaGetSymbolAddress((void**)&p_x1,        g_x1);

    const int SMEM = 2 * (128 + 64) * PADK * 2;   // 55296 B
    cudaFuncSetAttribute(mma_gemm<0, false, 2, true>,  cudaFuncAttributeMaxDynamicSharedMemorySize, SMEM);
    cudaFuncSetAttribute(mma_gemm<0, false, 1, true>,  cudaFuncAttributeMaxDynamicSharedMemorySize, SMEM);
    cudaFuncSetAttribute(mma_gemm<1, false, 1, true>,  cudaFuncAttributeMaxDynamicSharedMemorySize, SMEM);
    cudaFuncSetAttribute(mma_gemm<0, true, 0, false>,  cudaFuncAttributeMaxDynamicSharedMemorySize, SMEM);

    // 0) fused weight convert + fragment-ordered bias/mask table
    prep_kernel<<<768, 256>>>(qkv_w, proj_w, fc1_w, fc2_w, rpb);
    // 1) LN1 + shift + partition
    ln_gather_kernel<<<8192, 256>>>(x, ln1_g, ln1_b);
    // 2) QKV GEMM -> head-major fp16 (q pre-scaled)
    mma_gemm<0, false, 2, true><<<dim3(6, 512), 256, SMEM>>>(
        p_win, p_qkvw, qkv_b, nullptr, nullptr, p_qkvh, 384, 128);
    // 3) attention
    attn_kernel<<<NWIN * NH_ * 2, 128>>>();
    // 4) proj GEMM -> fp16
    mma_gemm<0, false, 1, true><<<dim3(2, 512), 256, SMEM>>>(
        p_attn, p_projw, proj_b, nullptr, nullptr, p_projout_h, 128, 128);
    // 5) reverse + roll + residual + LN2
    scatter_ln2_kernel<<<8192, 256>>>(x, ln2_g, ln2_b);
    // 6) fc1 + GELU -> fp16
    mma_gemm<1, false, 1, true><<<dim3(8, 512), 256, SMEM>>>(
        p_xn2, p_fc1w, fc1_b, nullptr, nullptr, p_hid, 512, 128);
    // 7) fc2 + residual -> out (f32)
    mma_gemm<0, true, 0, false><<<dim3(2, 512), 256, SMEM>>>(
        p_hid, p_fc2w, fc2_b, p_x1, out, nullptr, 128, 512);
}

// round 17
// speedup vs baseline: 1.4595x; 1.0120x over previous
#include <cuda_runtime.h>
#include <cuda_fp16.h>
#include <math.h>
#include <stdint.h>

// Problem constants
#define B_    2
#define D_    8
#define C_    128
#define NH_   8
#define NTOK  65536
#define NWIN  512
#define NN_   128
#define MLPH  512
#define LOG2E 1.4426950408889634f

// ---------------- scratch (device globals) -----------------------------------
__device__ half  g_win[NTOK * C_];
__device__ half  g_qkvh[24LL * NTOK * 16];     // [part(3)][head(8)][tok][16]
__device__ uint4 g_tblF[131072];               // [cls][h][rb][j2][lane] fragment-order
__device__ half  g_attn[NTOK * C_];
__device__ half  g_projout_h[NTOK * C_];
__device__ float g_x1[NTOK * C_];
__device__ half  g_xn2[NTOK * C_];
__device__ half  g_hid[(long)NTOK * MLPH];
// fp16 weights
__device__ half  g_qkvw[384 * C_];
__device__ half  g_projw[C_ * C_];
__device__ half  g_fc1w[MLPH * C_];
__device__ half  g_fc2w[C_ * MLPH];

__device__ __forceinline__ float gelu_exact(float x) {
    return 0.5f * x * (1.0f + erff(x * 0.70710678118654752f));
}

// ---- mma.sync m16n8k16 f16 -> f32 ------------------------------------------------
#define MMA(d, a, b)                                                            \
    asm volatile("mma.sync.aligned.m16n8k16.row.col.f32.f16.f16.f32 "           \
        "{%0,%1,%2,%3}, {%4,%5,%6,%7}, {%8,%9}, {%0,%1,%2,%3};"                 \
        : "+f"((d)[0]), "+f"((d)[1]), "+f"((d)[2]), "+f"((d)[3])                \
        : "r"((a)[0]), "r"((a)[1]), "r"((a)[2]), "r"((a)[3]),                    \
          "r"((b)[0]), "r"((b)[1]))

#define LDMX4(r, addr)                                                          \
    asm volatile("ldmatrix.sync.aligned.m8n8.x4.shared.b16 {%0,%1,%2,%3}, [%4];"\
        : "=r"((r)[0]), "=r"((r)[1]), "=r"((r)[2]), "=r"((r)[3]) : "r"(addr))

__device__ __forceinline__ uint32_t smem_u32(const void* p) {
    uint32_t a;
    asm("{ .reg .u64 t; cvta.to.shared.u64 t, %1; cvt.u32.u64 %0, t; }" : "=r"(a) : "l"(p));
    return a;
}
__device__ __forceinline__ void cpa16(uint32_t d, const void* s) {
    asm volatile("cp.async.cg.shared.global [%0], [%1], 16;" :: "r"(d), "l"(s));
}
#define CP_COMMIT() asm volatile("cp.async.commit_group;" ::: "memory")
#define CP_WAIT0()  asm volatile("cp.async.wait_group 0;" ::: "memory")
#define CP_WAIT1()  asm volatile("cp.async.wait_group 1;" ::: "memory")

// ==================  GEMM: BM=128 BN=64 BK=64, 256 thr, 3 CTAs/SM  ================
#define PADK 72
#define BUFA (128 * PADK * 2)
#define BUFW (64 * PADK * 2)

template <int ACT, bool RES, int OMODE, bool FULLK>
__global__ void __launch_bounds__(256, 3)
mma_gemm(const half* __restrict__ A, const half* __restrict__ W,
         const float* __restrict__ bias, const float* __restrict__ res,
         float* __restrict__ Cf, half* __restrict__ Chf,
         int N, int K) {
    extern __shared__ half smem[];
    half* sA = smem;
    half* sW = smem + 2 * 128 * PADK;
    uint32_t sAu = smem_u32(sA), sWu = smem_u32(sW);

    int tid = threadIdx.x, wid = tid >> 5, lane = tid & 31;
    int g = lane >> 2, t = lane & 3;
    int m0 = blockIdx.y * 128, n0 = blockIdx.x * 64;
    int wm = (wid >> 1) * 32, wn = (wid & 1) * 32;

    float acc[2][4][4];
#pragma unroll
    for (int i = 0; i < 2; i++)
#pragma unroll
        for (int j = 0; j < 4; j++)
#pragma unroll
            for (int c = 0; c < 4; c++) acc[i][j][c] = 0.0f;

    int crow = tid >> 3, cseg = (tid & 7) * 8;
    auto issue = [&](int kc, int buf) {
#pragma unroll
        for (int i = 0; i < 4; i++) {
            int row = crow + i * 32;
            cpa16(sAu + (uint32_t)buf * BUFA + (row * PADK + cseg) * 2,
                  A + (long)(m0 + row) * K + kc + cseg);
        }
#pragma unroll
        for (int i = 0; i < 2; i++) {
            int row = crow + i * 32;
            cpa16(sWu + (uint32_t)buf * BUFW + (row * PADK + cseg) * 2,
                  W + (long)(n0 + row) * K + kc + cseg);
        }
        CP_COMMIT();
    };

    int lrow = lane & 7, lsel = lane >> 3;
    uint32_t aBase = sAu + ((wm + (lsel & 1) * 8 + lrow) * PADK + (lsel >> 1) * 8) * 2;
    uint32_t bBase = sWu + ((wn + (lsel >> 1) * 8 + lrow) * PADK + (lsel & 1) * 8) * 2;

    auto compute_chunk = [&](uint32_t aofs, uint32_t wofs) {
#pragma unroll
        for (int ks = 0; ks < 4; ks++) {
            uint32_t kb2 = ks * 32;
            uint32_t fa[2][4], fb[4][2];
#pragma unroll
            for (int mi = 0; mi < 2; mi++)
                LDMX4(fa[mi], aBase + aofs + mi * (16 * PADK * 2) + kb2);
            LDMX4(fb[0], bBase + wofs + kb2);
            LDMX4(fb[2], bBase + wofs + 16 * PADK * 2 + kb2);
#pragma unroll
            for (int mi = 0; mi < 2; mi++)
#pragma unroll
                for (int nj = 0; nj < 4; nj++)
                    MMA(acc[mi][nj], fa[mi], fb[nj]);
        }
    };

    if (FULLK) {
        issue(0, 0);
        issue(64, 1);
        CP_WAIT0();
        __syncthreads();
        compute_chunk(0, 0);
        compute_chunk(BUFA, BUFW);
    } else {
        int nch = K >> 6;
        issue(0, 0);
        for (int c = 0; c < nch; c++) {
            if (c + 1 < nch) { issue((c + 1) << 6, (c + 1) & 1); CP_WAIT1(); }
            else             { CP_WAIT0(); }
            __syncthreads();
            compute_chunk((uint32_t)(c & 1) * BUFA, (uint32_t)(c & 1) * BUFW);
            __syncthreads();
        }
    }

#pragma unroll
    for (int mi = 0; mi < 2; mi++) {
#pragma unroll
        for (int cr = 0; cr < 2; cr++) {
            int m = m0 + wm + mi * 16 + g + cr * 8;
#pragma unroll
            for (int nj = 0; nj < 4; nj++) {
                int n = n0 + wn + nj * 8 + 2 * t;
                float2 bb = *(const float2*)(bias + n);
                float v0 = acc[mi][nj][cr * 2 + 0] + bb.x;
                float v1 = acc[mi][nj][cr * 2 + 1] + bb.y;
                if (OMODE == 2 && n < 128) {     // q: fold 0.25 * log2(e)
                    v0 *= 0.25f * LOG2E; v1 *= 0.25f * LOG2E;
                }
                if (ACT == 1) { v0 = gelu_exact(v0); v1 = gelu_exact(v1); }
                if (RES) {
                    float2 r = *(const float2*)(res + (long)m * N + n);
                    v0 += r.x; v1 += r.y;
                }
                if (OMODE == 2) {
                    int p = n >> 7, hh = (n >> 4) & 7, d = n & 15;
                    long addr = ((long)(p * 8 + hh) * NTOK + m) * 16 + d;
                    *(half2*)(Chf + addr) = __floats2half2_rn(v0, v1);
                } else if (OMODE == 1) {
                    *(half2*)(Chf + (long)m * N + n) = __floats2half2_rn(v0, v1);
                } else {
                    float2 o; o.x = v0; o.y = v1;
                    *(float2*)(Cf + (long)m * N + n) = o;
                }
            }
        }
    }
}

// ---------------- fused weight convert + fragment-ordered bias/mask table --------
// table entries pre-scaled by log2(e); mask = -100*log2e (exp2 -> exact 0)
__device__ __forceinline__ half tbl_entry(const float* rpb, int cls, int h,
                                          int n, int m) {
    int tdn = n >> 6, thn = (n >> 3) & 7, twn = n & 7;
    int tdm = m >> 6, thm = (m >> 3) & 7, twm = m & 7;
    int rpi = (tdn - tdm + 1) * 225 + (thn - thm + 7) * 15 + (twn - twm + 7);
    bool dd = tdn != tdm;
    bool dh = (thn < 4) != (thm < 4);
    bool dw = (twn < 4) != (twm < 4);
    float mask = (((cls & 4) && dd) || ((cls & 2) && dh) || ((cls & 1) && dw))
                     ? -100.0f : 0.0f;
    return __float2half((rpb[rpi * NH_ + h] + mask) * LOG2E);
}

__global__ void prep_kernel(const float* __restrict__ qkv_w,
                            const float* __restrict__ proj_w,
                            const float* __restrict__ fc1_w,
                            const float* __restrict__ fc2_w,
                            const float* __restrict__ rpb) {
    int blk = blockIdx.x;
    int tid = threadIdx.x;
    if (blk < 256) {
        int i = blk * 256 + tid;
        if (i < 49152) g_qkvw[i] = __float2half(qkv_w[i]);
        if (i < 16384) g_projw[i] = __float2half(proj_w[i]);
        g_fc1w[i] = __float2half(fc1_w[i]);
        g_fc2w[i] = __float2half(fc2_w[i]);
    } else {
        int idx = (blk - 256) * 256 + tid;   // 0..131071
        int lane = idx & 31;
        int j2   = (idx >> 5) & 7;
        int rb   = (idx >> 8) & 7;
        int h    = (idx >> 11) & 7;
        int cls  = (idx >> 14) & 7;
        int g = lane >> 2, t = lane & 3;
        int row  = rb * 16 + g;
        half v[8];
#pragma unroll
        for (int jj = 0; jj < 2; jj++) {
            int col = 8 * (2 * j2 + jj) + 2 * t;
            v[jj * 4 + 0] = tbl_entry(rpb, cls, h, row,     col);
            v[jj * 4 + 1] = tbl_entry(rpb, cls, h, row,     col + 1);
            v[jj * 4 + 2] = tbl_entry(rpb, cls, h, row + 8, col);
            v[jj * 4 + 3] = tbl_entry(rpb, cls, h, row + 8, col + 1);
        }
        g_tblF[idx] = *(uint4*)v;
    }
}

// ---------------- K1: LN1 + cyclic shift + window partition (-> fp16) ------------
__global__ void ln_gather_kernel(const float* __restrict__ x,
                                 const float* __restrict__ g,
                                 const float* __restrict__ b) {
    int warp = (blockIdx.x * blockDim.x + threadIdx.x) >> 5;
    int lane = threadIdx.x & 31;
    if (warp >= NWIN * NN_) return;
    int bw = warp >> 7;
    int n  = warp & 127;
    int bb = bw >> 8;
    int wi = bw & 255;
    int wd = wi >> 6, wh = (wi >> 3) & 7, ww = wi & 7;
    int td = n >> 6,  th = (n >> 3) & 7, tw = n & 7;
    int gd = (wd * 2 + td + 1) & 7;
    int gh = (wh * 8 + th + 4) & 63;
    int gw = (ww * 8 + tw + 4) & 63;
    long src = (((long)(bb * D_ + gd) * 64 + gh) * 64 + gw) * C_;

    float4 v = *(const float4*)(x + src + lane * 4);
    float s  = v.x + v.y + v.z + v.w;
    float sq = v.x * v.x + v.y * v.y + v.z * v.z + v.w * v.w;
#pragma unroll
    for (int o = 16; o > 0; o >>= 1) {
        s  += __shfl_xor_sync(0xffffffffu, s, o);
        sq += __shfl_xor_sync(0xffffffffu, sq, o);
    }
    float mean = s * (1.0f / C_);
    float var  = sq * (1.0f / C_) - mean * mean;
    float inv  = rsqrtf(var + 1e-5f);
    float4 gg = *(const float4*)(g + lane * 4);
    float4 bv = *(const float4*)(b + lane * 4);
    long o = (long)warp * C_ + lane * 4;
    *(half2*)(g_win + o)     = __floats2half2_rn((v.x - mean) * inv * gg.x + bv.x,
                                                 (v.y - mean) * inv * gg.y + bv.y);
    *(half2*)(g_win + o + 2) = __floats2half2_rn((v.z - mean) * inv * gg.z + bv.z,
                                                 (v.w - mean) * inv * gg.w + bv.w);
}

// ---------------- K3: attention — fused QK+softmax in half2, P kept as fragments --
#define VPAD 136
__global__ void __launch_bounds__(128, 6) attn_kernel() {
    __shared__ half sVt[16 * VPAD];
    __shared__ half sK[128 * 16];

    int bw = blockIdx.x >> 4;
    int h  = (blockIdx.x >> 1) & 7;
    int rh = blockIdx.x & 1;
    int tid = threadIdx.x, wid = tid >> 5, lane = tid & 31;
    int g = lane >> 2, t = lane & 3;
    long tokbase = (long)bw * 128;
    const half* Qp = g_qkvh + ((long)h * NTOK + tokbase) * 16;
    const half* Kp = g_qkvh + ((long)(8 + h) * NTOK + tokbase) * 16;
    const half* Vp = g_qkvh + ((long)(16 + h) * NTOK + tokbase) * 16;

    {
        int tok = tid;
        uint4 kv0 = *(const uint4*)(Kp + tok * 16);
        uint4 kv1 = *(const uint4*)(Kp + tok * 16 + 8);
        *(uint4*)&sK[tok * 16]     = kv0;
        *(uint4*)&sK[tok * 16 + 8] = kv1;
        uint4 hv0 = *(const uint4*)(Vp + tok * 16);
        uint4 hv1 = *(const uint4*)(Vp + tok * 16 + 8);
        const half* h0 = (const half*)&hv0;
        const half* h1 = (const half*)&hv1;
#pragma unroll
        for (int d = 0; d < 8; d++) {
            sVt[d * VPAD + tok]       = h0[d];
            sVt[(8 + d) * VPAD + tok] = h1[d];
        }
    }
    __syncthreads();

    int row0 = rh * 64 + wid * 16;
    uint32_t qf[4];
    qf[0] = *(const uint32_t*)(Qp + (row0 + g) * 16 + 2 * t);
    qf[1] = *(const uint32_t*)(Qp + (row0 + g + 8) * 16 + 2 * t);
    qf[2] = *(const uint32_t*)(Qp + (row0 + g) * 16 + 2 * t + 8);
    qf[3] = *(const uint32_t*)(Qp + (row0 + g + 8) * 16 + 2 * t + 8);

    // fragment-ordered bias pointer
    int wi = bw & 255;
    int cls = (((wi >> 6) == 3) ? 4 : 0) | ((((wi >> 3) & 7) == 7) ? 2 : 0) |
              (((wi & 7) == 7) ? 1 : 0);
    int rb = rh * 4 + wid;
    const uint4* bF = g_tblF + ((((long)cls * 8 + h) * 8 + rb) * 8) * 32 + lane;

    // fused QK^T + bias + exp2 (fp16x2); P kept as PV fragments
    half2 ph[16][2];
    float sum_g = 0.0f, sum_g8 = 0.0f;
    uint4 bv4;
#pragma unroll
    for (int j = 0; j < 16; j++) {
        uint32_t kf[2];
        kf[0] = *(const uint32_t*)&sK[(8 * j + g) * 16 + 2 * t];
        kf[1] = *(const uint32_t*)&sK[(8 * j + g) * 16 + 2 * t + 8];
        float a4[4] = {0.0f, 0.0f, 0.0f, 0.0f};
        MMA(a4, qf, kf);
        if ((j & 1) == 0) bv4 = bF[(j >> 1) * 32];
        const half2* hp = (const half2*)&bv4;
        int jj = j & 1;
        half2 p0 = h2exp2(__hadd2(__floats2half2_rn(a4[0], a4[1]), hp[jj * 2 + 0]));
        half2 p1 = h2exp2(__hadd2(__floats2half2_rn(a4[2], a4[3]), hp[jj * 2 + 1]));
        ph[j][0] = p0;
        ph[j][1] = p1;
        float2 f0 = __half22float2(p0);
        float2 f1 = __half22float2(p1);
        sum_g  += f0.x + f0.y;
        sum_g8 += f1.x + f1.y;
    }
    sum_g  += __shfl_xor_sync(0xffffffffu, sum_g, 1);
    sum_g  += __shfl_xor_sync(0xffffffffu, sum_g, 2);
    sum_g8 += __shfl_xor_sync(0xffffffffu, sum_g8, 1);
    sum_g8 += __shfl_xor_sync(0xffffffffu, sum_g8, 2);
    float rs_g = 1.0f / sum_g, rs_g8 = 1.0f / sum_g8;

    // P @ V — fragments straight from ph
    float oacc[2][4];
#pragma unroll
    for (int nj = 0; nj < 2; nj++)
#pragma unroll
        for (int c = 0; c < 4; c++) oacc[nj][c] = 0.0f;

#pragma unroll
    for (int kt = 0; kt < 8; kt++) {
        uint32_t pf[4];
        pf[0] = *(uint32_t*)&ph[2 * kt][0];
        pf[1] = *(uint32_t*)&ph[2 * kt][1];
        pf[2] = *(uint32_t*)&ph[2 * kt + 1][0];
        pf[3] = *(uint32_t*)&ph[2 * kt + 1][1];
#pragma unroll
        for (int nj = 0; nj < 2; nj++) {
            int vb = (8 * nj + g) * VPAD + 16 * kt + 2 * t;
            uint32_t vf[2];
            vf[0] = *(const uint32_t*)&sVt[vb];
            vf[1] = *(const uint32_t*)&sVt[vb + 8];
            MMA(oacc[nj], pf, vf);
        }
    }

    long og  = (tokbase + row0 + g) * 128 + h * 16;
    long og8 = og + 8 * 128;
#pragma unroll
    for (int nj = 0; nj < 2; nj++) {
        int dn = 8 * nj + 2 * t;
        *(half2*)(g_attn + og + dn)  = __floats2half2_rn(oacc[nj][0] * rs_g,
                                                         oacc[nj][1] * rs_g);
        *(half2*)(g_attn + og8 + dn) = __floats2half2_rn(oacc[nj][2] * rs_g8,
                                                         oacc[nj][3] * rs_g8);
    }
}

// -------- K6: window-reverse + roll + residual + LN2 (-> x1 f32, xn2 fp16) -------
__global__ void scatter_ln2_kernel(const float* __restrict__ x,
                                   const float* __restrict__ g2,
                                   const float* __restrict__ b2) {
    int tk = (blockIdx.x * blockDim.x + threadIdx.x) >> 5;
    int lane = threadIdx.x & 31;
    if (tk >= NTOK) return;
    int w = tk & 63, h = (tk >> 6) & 63, d = (tk >> 12) & 7, bb = tk >> 15;
    int sd = (d + 7) & 7;
    int sh = (h + 60) & 63;
    int sw = (w + 60) & 63;
    int bw = bb * 256 + (sd >> 1) * 64 + (sh >> 3) * 8 + (sw >> 3);
    int n  = (sd & 1) * 64 + (sh & 7) * 8 + (sw & 7);

    float4 xv = *(const float4*)(x + (long)tk * C_ + lane * 4);
    uint2 pvh = *(const uint2*)(g_projout_h + ((long)bw * NN_ + n) * C_ + lane * 4);
    float2 p01 = __half22float2(*(half2*)&pvh.x);
    float2 p23 = __half22float2(*(half2*)&pvh.y);
    float4 s1;
    s1.x = xv.x + p01.x; s1.y = xv.y + p01.y;
    s1.z = xv.z + p23.x; s1.w = xv.w + p23.y;
    *(float4*)(g_x1 + (long)tk * C_ + lane * 4) = s1;

    float s  = s1.x + s1.y + s1.z + s1.w;
    float sq = s1.x * s1.x + s1.y * s1.y + s1.z * s1.z + s1.w * s1.w;
#pragma unroll
    for (int o = 16; o > 0; o >>= 1) {
        s  += __shfl_xor_sync(0xffffffffu, s, o);
        sq += __shfl_xor_sync(0xffffffffu, sq, o);
    }
    float mean = s * (1.0f / C_);
    float var  = sq * (1.0f / C_) - mean * mean;
    float inv  = rsqrtf(var + 1e-5f);
    float4 gg = *(const float4*)(g2 + lane * 4);
    float4 bv = *(const float4*)(b2 + lane * 4);
    long o = (long)tk * C_ + lane * 4;
    *(half2*)(g_xn2 + o)     = __floats2half2_rn((s1.x - mean) * inv * gg.x + bv.x,
                                                 (s1.y - mean) * inv * gg.y + bv.y);
    *(half2*)(g_xn2 + o + 2) = __floats2half2_rn((s1.z - mean) * inv * gg.z + bv.z,
                                                 (s1.w - mean) * inv * gg.w + bv.w);
}

// ---------------------------------------------------------------------------
extern "C" void kernel_launch(void* const* d_in, const int* in_sizes, int n_in,
                              void* d_out, int out_size) {
    const float* x      = (const float*)d_in[0];
    const float* qkv_w  = (const float*)d_in[1];
    const float* qkv_b  = (const float*)d_in[2];
    const float* proj_w = (const float*)d_in[3];
    const float* proj_b = (const float*)d_in[4];
    const float* rpb    = (const float*)d_in[5];
    const float* ln1_g  = (const float*)d_in[6];
    const float* ln1_b  = (const float*)d_in[7];
    const float* ln2_g  = (const float*)d_in[8];
    const float* ln2_b  = (const float*)d_in[9];
    const float* fc1_w  = (const float*)d_in[10];
    const float* fc1_b  = (const float*)d_in[11];
    const float* fc2_w  = (const float*)d_in[12];
    const float* fc2_b  = (const float*)d_in[13];
    float* out = (float*)d_out;

    half *p_win, *p_qkvh, *p_attn, *p_projout_h, *p_xn2, *p_hid;
    half *p_qkvw, *p_projw, *p_fc1w, *p_fc2w;
    float *p_x1;
    cudaGetSymbolAddress((void**)&p_win,       g_win);
    cudaGetSymbolAddress((void**)&p_qkvh,      g_qkvh);
    cudaGetSymbolAddress((void**)&p_attn,      g_attn);
    cudaGetSymbolAddress((void**)&p_projout_h, g_projout_h);
    cudaGetSymbolAddress((void**)&p_xn2,       g_xn2);
    cudaGetSymbolAddress((void**)&p_hid,       g_hid);
    cudaGetSymbolAddress((void**)&p_qkvw,      g_qkvw);
    cudaGetSymbolAddress((void**)&p_projw,     g_projw);
    cudaGetSymbolAddress((void**)&p_fc1w,      g_fc1w);
    cudaGetSymbolAddress((void**)&p_fc2w,      g_fc2w);
    cudaGetSymbolAddress((void**)&p_x1,        g_x1);

    const int SMEM = 2 * (128 + 64) * PADK * 2;   // 55296 B
    cudaFuncSetAttribute(mma_gemm<0, false, 2, true>,  cudaFuncAttributeMaxDynamicSharedMemorySize, SMEM);
    cudaFuncSetAttribute(mma_gemm<0, false, 1, true>,  cudaFuncAttributeMaxDynamicSharedMemorySize, SMEM);
    cudaFuncSetAttribute(mma_gemm<1, false, 1, true>,  cudaFuncAttributeMaxDynamicSharedMemorySize, SMEM);
    cudaFuncSetAttribute(mma_gemm<0, true, 0, false>,  cudaFuncAttributeMaxDynamicSharedMemorySize, SMEM);

    // 0) fused weight convert + fragment-ordered bias/mask table (log2e-scaled)
    prep_kernel<<<768, 256>>>(qkv_w, proj_w, fc1_w, fc2_w, rpb);
    // 1) LN1 + shift + partition
    ln_gather_kernel<<<8192, 256>>>(x, ln1_g, ln1_b);
    // 2) QKV GEMM -> head-major fp16 (q pre-scaled by 0.25*log2e)
    mma_gemm<0, false, 2, true><<<dim3(6, 512), 256, SMEM>>>(
        p_win, p_qkvw, qkv_b, nullptr, nullptr, p_qkvh, 384, 128);
    // 3) attention
    attn_kernel<<<NWIN * NH_ * 2, 128>>>();
    // 4) proj GEMM -> fp16
    mma_gemm<0, false, 1, true><<<dim3(2, 512), 256, SMEM>>>(
        p_attn, p_projw, proj_b, nullptr, nullptr, p_projout_h, 128, 128);
    // 5) reverse + roll + residual + LN2
    scatter_ln2_kernel<<<8192, 256>>>(x, ln2_g, ln2_b);
    // 6) fc1 + GELU -> fp16
    mma_gemm<1, false, 1, true><<<dim3(8, 512), 256, SMEM>>>(
        p_xn2, p_fc1w, fc1_b, nullptr, nullptr, p_hid, 512, 128);
    // 7) fc2 + residual -> out (f32)
    mma_gemm<0, true, 0, false><<<dim3(2, 512), 256, SMEM>>>(
        p_hid, p_fc2w, fc2_b, p_x1, out, nullptr, 128, 512);
}